// round 6
// baseline (speedup 1.0000x reference)
#include <cuda_runtime.h>
#include <cuda_bf16.h>
#include <math_constants.h>
#include <cstdint>

#define B_ 8
#define S_ 1024
#define H_ 1024
#define NH_ 16
#define HD_ 64
#define M_ (B_ * S_)        // 8192
#define LN_EPS 1e-12f

// fp32 scratch
__device__ float g_x[M_ * H_];    // residual-added pre-LN

// bf16 hi/lo split scratch (u16 bits)
__device__ unsigned short g_Xhi[M_ * H_];
__device__ unsigned short g_Xlo[M_ * H_];
__device__ unsigned short g_Whi[4 * H_ * H_];   // Wq,Wk,Wv,Wo
__device__ unsigned short g_Wlo[4 * H_ * H_];
__device__ unsigned short g_Qh[M_ * H_];        // [B*NH][S][HD]
__device__ unsigned short g_Ql[M_ * H_];
__device__ unsigned short g_Kh[M_ * H_];
__device__ unsigned short g_Kl[M_ * H_];
__device__ unsigned short g_Vh[M_ * H_];
__device__ unsigned short g_Vl[M_ * H_];
__device__ unsigned short g_Chi[M_ * H_];       // ctx split [B,S,H]
__device__ unsigned short g_Clo[M_ * H_];

// ---------------------------------------------------------------------------
// helpers (family-agnostic PTX: ldmatrix sm_75+, mma.sync bf16 + cp.async sm_80+)
// ---------------------------------------------------------------------------
__device__ __forceinline__ uint32_t smem_u32(const void* p) {
    uint32_t a;
    asm("{ .reg .u64 t; cvta.to.shared.u64 t, %1; cvt.u32.u64 %0, t; }" : "=r"(a) : "l"(p));
    return a;
}
__device__ __forceinline__ void ldm_x4(uint32_t& r0, uint32_t& r1, uint32_t& r2, uint32_t& r3,
                                       uint32_t addr) {
    asm volatile("ldmatrix.sync.aligned.m8n8.x4.shared.b16 {%0,%1,%2,%3}, [%4];"
                 : "=r"(r0), "=r"(r1), "=r"(r2), "=r"(r3) : "r"(addr));
}
__device__ __forceinline__ void ldm_x4_t(uint32_t& r0, uint32_t& r1, uint32_t& r2, uint32_t& r3,
                                         uint32_t addr) {
    asm volatile("ldmatrix.sync.aligned.m8n8.x4.trans.shared.b16 {%0,%1,%2,%3}, [%4];"
                 : "=r"(r0), "=r"(r1), "=r"(r2), "=r"(r3) : "r"(addr));
}
__device__ __forceinline__ void mma_bf16(float* d, const uint32_t* a, const uint32_t* b) {
    asm volatile(
        "mma.sync.aligned.m16n8k16.row.col.f32.bf16.bf16.f32 "
        "{%0,%1,%2,%3}, {%4,%5,%6,%7}, {%8,%9}, {%0,%1,%2,%3};"
        : "+f"(d[0]), "+f"(d[1]), "+f"(d[2]), "+f"(d[3])
        : "r"(a[0]), "r"(a[1]), "r"(a[2]), "r"(a[3]), "r"(b[0]), "r"(b[1]));
}
__device__ __forceinline__ void cp16(uint32_t dst, const void* src) {
    asm volatile("cp.async.cg.shared.global [%0], [%1], 16;" :: "r"(dst), "l"(src));
}
__device__ __forceinline__ void cp_commit() { asm volatile("cp.async.commit_group;"); }
// split two fp32 into packed bf16x2 hi + bf16x2 lo
__device__ __forceinline__ void pack_split(float a, float b, uint32_t& hi, uint32_t& lo) {
    __nv_bfloat16 ha = __float2bfloat16(a), hb = __float2bfloat16(b);
    __nv_bfloat16 la = __float2bfloat16(a - __bfloat162float(ha));
    __nv_bfloat16 lb = __float2bfloat16(b - __bfloat162float(hb));
    hi = (uint32_t)__bfloat16_as_ushort(ha) | ((uint32_t)__bfloat16_as_ushort(hb) << 16);
    lo = (uint32_t)__bfloat16_as_ushort(la) | ((uint32_t)__bfloat16_as_ushort(lb) << 16);
}

// ---------------------------------------------------------------------------
// split fp32 -> bf16 hi + bf16 lo (X and weights)
// ---------------------------------------------------------------------------
__global__ __launch_bounds__(256) void split_kernel(
    const float* __restrict__ src, unsigned short* __restrict__ hi,
    unsigned short* __restrict__ lo, int n4)
{
    int i = blockIdx.x * 256 + threadIdx.x;
    if (i >= n4) return;
    float4 v = ((const float4*)src)[i];
    float f[4] = {v.x, v.y, v.z, v.w};
    ushort4 hh, ll;
    unsigned short* hp = &hh.x;
    unsigned short* lp = &ll.x;
    #pragma unroll
    for (int j = 0; j < 4; j++) {
        __nv_bfloat16 h = __float2bfloat16(f[j]);
        float r = f[j] - __bfloat162float(h);
        __nv_bfloat16 l = __float2bfloat16(r);
        hp[j] = __bfloat16_as_ushort(h);
        lp[j] = __bfloat16_as_ushort(l);
    }
    ((ushort4*)hi)[i] = hh;
    ((ushort4*)lo)[i] = ll;
}

// ---------------------------------------------------------------------------
// cp.async 3-stage split-bf16 GEMM: C[m][n] = sum_k A[m][k]*W[n][k]
// BM=128 BN=128 BK=32, 256 thr (8 warps 4x2), warp tile 32x64, 3 mma passes.
// ---------------------------------------------------------------------------
#define BK 32
#define NCH (H_ / BK)        // 32
#define STR 40               // smem row stride (halves)
#define MAT_H (128 * STR)
#define STG_H (4 * MAT_H)
#define GEMM_SMEM (3 * STG_H * 2)

__global__ __launch_bounds__(256, 1) void gemm_kernel(
    const unsigned short* __restrict__ Ahi, const unsigned short* __restrict__ Alo,
    int wbase,
    const float* __restrict__ bias0, const float* __restrict__ bias1,
    const float* __restrict__ bias2, const float* __restrict__ residual)
{
    extern __shared__ unsigned short sm[];
    const uint32_t sbase = smem_u32(sm);

    const int tid = threadIdx.x;
    const int wid = tid >> 5;
    const int lane = tid & 31;
    const int warp_m = wid & 3;
    const int warp_n = wid >> 2;
    const int w  = wbase + blockIdx.z;
    const int n0 = blockIdx.x * 128;
    const int m0 = blockIdx.y * 128;

    const unsigned short* Bhi = g_Whi + ((size_t)w << 20);
    const unsigned short* Blo = g_Wlo + ((size_t)w << 20);
    const float* bias = (w == 1) ? bias1 : (w == 2) ? bias2 : bias0;

    const unsigned short* gsrc[4] = {Ahi, Alo, Bhi, Blo};
    const int gbase[4] = {m0, m0, n0, n0};

    // cp.async mapping: 2048 16B transfers per stage, 8 per thread
    // v = tid + t*256: mat=v>>9, rem=v&511, row=rem>>2, g=(rem&3)*8
    const int cp_mat[8] = {tid >> 9 | 0, 0, 0, 0, 0, 0, 0, 0}; // placeholder (computed in loop)

    auto issue_stage = [&](int c) {
        const int st = c % 3;
        const int kc = c * BK;
        #pragma unroll
        for (int t = 0; t < 8; t++) {
            int v = tid + t * 256;
            int mat = v >> 9;
            int rem = v & 511;
            int row = rem >> 2;
            int g = (rem & 3) * 8;
            const unsigned short* src = gsrc[mat] + (size_t)(gbase[mat] + row) * H_ + kc + g;
            uint32_t dst = sbase + (uint32_t)(st * STG_H + mat * MAT_H + row * STR + g) * 2;
            cp16(dst, src);
        }
        cp_commit();
    };

    float C[2][8][4];
    #pragma unroll
    for (int a = 0; a < 2; a++)
        #pragma unroll
        for (int b = 0; b < 8; b++)
            #pragma unroll
            for (int c = 0; c < 4; c++) C[a][b][c] = 0.f;

    issue_stage(0);
    issue_stage(1);

    for (int c = 0; c < NCH; c++) {
        if (c + 1 < NCH) { asm volatile("cp.async.wait_group 1;" ::: "memory"); }
        else             { asm volatile("cp.async.wait_group 0;" ::: "memory"); }
        __syncthreads();

        if (c + 2 < NCH) issue_stage(c + 2);

        const uint32_t stage = sbase + (uint32_t)(c % 3) * (STG_H * 2);

        #pragma unroll
        for (int ks = 0; ks < 2; ks++) {
            const int k0 = ks * 16;
            uint32_t ah[2][4], al[2][4];
            #pragma unroll
            for (int mt = 0; mt < 2; mt++) {
                int row = warp_m * 32 + mt * 16 + (lane & 15);
                int col = k0 + (lane >> 4) * 8;
                uint32_t off = (uint32_t)(row * STR + col) * 2;
                ldm_x4(ah[mt][0], ah[mt][1], ah[mt][2], ah[mt][3],
                       stage + 0 * MAT_H * 2 + off);
                ldm_x4(al[mt][0], al[mt][1], al[mt][2], al[mt][3],
                       stage + 1 * MAT_H * 2 + off);
            }
            #pragma unroll
            for (int ntp = 0; ntp < 4; ntp++) {
                int brow = warp_n * 64 + ntp * 16 + (lane & 7) + (lane >> 4) * 8;
                int bcol = k0 + ((lane >> 3) & 1) * 8;
                uint32_t off = (uint32_t)(brow * STR + bcol) * 2;
                uint32_t bh[4], bl[4];
                ldm_x4(bh[0], bh[1], bh[2], bh[3], stage + 2 * MAT_H * 2 + off);
                ldm_x4(bl[0], bl[1], bl[2], bl[3], stage + 3 * MAT_H * 2 + off);
                #pragma unroll
                for (int nt2 = 0; nt2 < 2; nt2++) {
                    const int nt = ntp * 2 + nt2;
                    #pragma unroll
                    for (int mt = 0; mt < 2; mt++) {
                        mma_bf16(C[mt][nt], ah[mt], &bh[nt2 * 2]);
                        mma_bf16(C[mt][nt], ah[mt], &bl[nt2 * 2]);
                        mma_bf16(C[mt][nt], al[mt], &bh[nt2 * 2]);
                    }
                }
            }
        }
        __syncthreads();
    }

    // epilogue
    unsigned short* oh = (w == 0) ? g_Qh : (w == 1) ? g_Kh : g_Vh;
    unsigned short* ol = (w == 0) ? g_Ql : (w == 1) ? g_Kl : g_Vl;
    #pragma unroll
    for (int mt = 0; mt < 2; mt++) {
        #pragma unroll
        for (int nt = 0; nt < 8; nt++) {
            const float* d = C[mt][nt];
            int m = m0 + warp_m * 32 + mt * 16 + (lane >> 2);
            int n = n0 + warp_n * 64 + nt * 8 + (lane & 3) * 2;
            float b0 = bias[n], b1 = bias[n + 1];
            if (w < 3) {
                int h = n >> 6, dd = n & 63;
                #pragma unroll
                for (int rr = 0; rr < 2; rr++) {
                    int mm = m + rr * 8;
                    int bb = mm >> 10, ss = mm & 1023;
                    size_t o = ((size_t)(bb * NH_ + h) * S_ + ss) * HD_ + dd;
                    uint32_t hi, lo;
                    pack_split(d[rr * 2 + 0] + b0, d[rr * 2 + 1] + b1, hi, lo);
                    *(uint32_t*)&oh[o] = hi;
                    *(uint32_t*)&ol[o] = lo;
                }
            } else {
                #pragma unroll
                for (int rr = 0; rr < 2; rr++) {
                    int mm = m + rr * 8;
                    size_t idx = (size_t)mm * H_ + n;
                    float2 res = *(const float2*)&residual[idx];
                    float2 o = make_float2(d[rr * 2 + 0] + b0 + res.x,
                                           d[rr * 2 + 1] + b1 + res.y);
                    *(float2*)&g_x[idx] = o;
                }
            }
        }
    }
}

// ---------------------------------------------------------------------------
// Tensor-core flash attention, split-bf16, fp32 softmax.
// grid (S/128=8, B*NH=128), 256 thr (8 warps, 16 q-rows each).
// ---------------------------------------------------------------------------
#define ASTR 72   // smem row stride (u16)

__global__ __launch_bounds__(256) void attn_kernel(const float* __restrict__ mask)
{
    __shared__ unsigned short Kh[64 * ASTR], Kl[64 * ASTR];
    __shared__ unsigned short Vh[64 * ASTR], Vl[64 * ASTR];
    __shared__ float msk[S_];

    const int bh  = blockIdx.y;
    const int qt  = blockIdx.x;
    const int tid = threadIdx.x;
    const int wid = tid >> 5;
    const int lane = tid & 31;
    const int b   = bh >> 4;
    const int h   = bh & 15;
    const size_t base = (size_t)bh * S_ * HD_;

    const uint32_t sKh = smem_u32(Kh), sKl = smem_u32(Kl);
    const uint32_t sVh = smem_u32(Vh), sVl = smem_u32(Vl);

    // mask row -> smem (1024 floats, 256 threads)
    ((float4*)msk)[tid] = ((const float4*)(mask + (size_t)b * S_))[tid];

    // stage Q (128 rows): hi -> Kh(0-63)/Vh(64-127), lo -> Kl/Vl
    #pragma unroll
    for (int t = 0; t < 4; t++) {
        int idx = tid + t * 256;            // 0..1023
        int row = idx >> 3, g = (idx & 7) * 8;
        size_t go = base + (size_t)(qt * 128 + row) * HD_ + g;
        unsigned short* dh = (row < 64) ? Kh : Vh;
        unsigned short* dl = (row < 64) ? Kl : Vl;
        int r = row & 63;
        *(uint4*)&dh[r * ASTR + g] = *(const uint4*)&g_Qh[go];
        *(uint4*)&dl[r * ASTR + g] = *(const uint4*)&g_Ql[go];
    }
    __syncthreads();

    uint32_t qh[4][4], ql[4][4];
    {
        const uint32_t bh_ = (wid < 4) ? sKh : sVh;
        const uint32_t bl_ = (wid < 4) ? sKl : sVl;
        int rbase = (wid & 3) * 16 + (lane & 15);
        #pragma unroll
        for (int ks = 0; ks < 4; ks++) {
            int col = ks * 16 + (lane >> 4) * 8;
            uint32_t off = (uint32_t)(rbase * ASTR + col) * 2;
            ldm_x4(qh[ks][0], qh[ks][1], qh[ks][2], qh[ks][3], bh_ + off);
            ldm_x4(ql[ks][0], ql[ks][1], ql[ks][2], ql[ks][3], bl_ + off);
        }
    }
    __syncthreads();

    float Co[8][4];
    #pragma unroll
    for (int i = 0; i < 8; i++)
        #pragma unroll
        for (int j = 0; j < 4; j++) Co[i][j] = 0.f;
    float m0 = -CUDART_INF_F, m1 = -CUDART_INF_F, l0 = 0.f, l1 = 0.f;

    for (int kt = 0; kt < S_ / 64; kt++) {
        // load K/V hi+lo tiles (64 rows each): 2048 uint4 stores, 8/thread
        #pragma unroll
        for (int t = 0; t < 2; t++) {
            int idx = tid + t * 256;        // 0..511
            int row = idx >> 3, g = (idx & 7) * 8;
            size_t go = base + (size_t)(kt * 64 + row) * HD_ + g;
            *(uint4*)&Kh[row * ASTR + g] = *(const uint4*)&g_Kh[go];
            *(uint4*)&Kl[row * ASTR + g] = *(const uint4*)&g_Kl[go];
            *(uint4*)&Vh[row * ASTR + g] = *(const uint4*)&g_Vh[go];
            *(uint4*)&Vl[row * ASTR + g] = *(const uint4*)&g_Vl[go];
        }
        __syncthreads();

        // S = Q K^T (3 split passes)
        float Cs[8][4];
        #pragma unroll
        for (int i = 0; i < 8; i++)
            #pragma unroll
            for (int j = 0; j < 4; j++) Cs[i][j] = 0.f;

        #pragma unroll
        for (int ks = 0; ks < 4; ks++) {
            #pragma unroll
            for (int ntp = 0; ntp < 4; ntp++) {
                int brow = ntp * 16 + (lane & 7) + (lane >> 4) * 8;
                int bcol = ks * 16 + ((lane >> 3) & 1) * 8;
                uint32_t off = (uint32_t)(brow * ASTR + bcol) * 2;
                uint32_t kbh[4], kbl[4];
                ldm_x4(kbh[0], kbh[1], kbh[2], kbh[3], sKh + off);
                ldm_x4(kbl[0], kbl[1], kbl[2], kbl[3], sKl + off);
                #pragma unroll
                for (int nt2 = 0; nt2 < 2; nt2++) {
                    const int nt = ntp * 2 + nt2;
                    mma_bf16(Cs[nt], qh[ks], &kbh[nt2 * 2]);
                    mma_bf16(Cs[nt], qh[ks], &kbl[nt2 * 2]);
                    mma_bf16(Cs[nt], ql[ks], &kbh[nt2 * 2]);
                }
            }
        }

        // scale + mask + online softmax
        float mn0 = m0, mn1 = m1;
        #pragma unroll
        for (int nt = 0; nt < 8; nt++) {
            int col = kt * 64 + nt * 8 + (lane & 3) * 2;
            float mka = msk[col], mkb = msk[col + 1];
            Cs[nt][0] = fmaf(Cs[nt][0], 0.125f, mka);
            Cs[nt][1] = fmaf(Cs[nt][1], 0.125f, mkb);
            Cs[nt][2] = fmaf(Cs[nt][2], 0.125f, mka);
            Cs[nt][3] = fmaf(Cs[nt][3], 0.125f, mkb);
            mn0 = fmaxf(mn0, fmaxf(Cs[nt][0], Cs[nt][1]));
            mn1 = fmaxf(mn1, fmaxf(Cs[nt][2], Cs[nt][3]));
        }
        mn0 = fmaxf(mn0, __shfl_xor_sync(0xffffffffu, mn0, 1));
        mn0 = fmaxf(mn0, __shfl_xor_sync(0xffffffffu, mn0, 2));
        mn1 = fmaxf(mn1, __shfl_xor_sync(0xffffffffu, mn1, 1));
        mn1 = fmaxf(mn1, __shfl_xor_sync(0xffffffffu, mn1, 2));

        float f0 = __expf(m0 - mn0), f1 = __expf(m1 - mn1);
        m0 = mn0; m1 = mn1;
        l0 *= f0; l1 *= f1;
        #pragma unroll
        for (int nt = 0; nt < 8; nt++) {
            Co[nt][0] *= f0; Co[nt][1] *= f0;
            Co[nt][2] *= f1; Co[nt][3] *= f1;
        }
        #pragma unroll
        for (int nt = 0; nt < 8; nt++) {
            Cs[nt][0] = __expf(Cs[nt][0] - m0);
            Cs[nt][1] = __expf(Cs[nt][1] - m0);
            Cs[nt][2] = __expf(Cs[nt][2] - m1);
            Cs[nt][3] = __expf(Cs[nt][3] - m1);
            l0 += Cs[nt][0] + Cs[nt][1];
            l1 += Cs[nt][2] + Cs[nt][3];
        }

        // O += P V (3 split passes)
        #pragma unroll
        for (int kc = 0; kc < 4; kc++) {
            uint32_t phi[4], plo[4];
            pack_split(Cs[2 * kc][0],     Cs[2 * kc][1],     phi[0], plo[0]);
            pack_split(Cs[2 * kc][2],     Cs[2 * kc][3],     phi[1], plo[1]);
            pack_split(Cs[2 * kc + 1][0], Cs[2 * kc + 1][1], phi[2], plo[2]);
            pack_split(Cs[2 * kc + 1][2], Cs[2 * kc + 1][3], phi[3], plo[3]);
            #pragma unroll
            for (int ntp = 0; ntp < 4; ntp++) {
                uint32_t off = (uint32_t)((kc * 16 + (lane & 15)) * ASTR +
                                          ntp * 16 + (lane >> 4) * 8) * 2;
                uint32_t vbh[4], vbl[4];
                ldm_x4_t(vbh[0], vbh[1], vbh[2], vbh[3], sVh + off);
                ldm_x4_t(vbl[0], vbl[1], vbl[2], vbl[3], sVl + off);
                #pragma unroll
                for (int nt2 = 0; nt2 < 2; nt2++) {
                    const int nt = ntp * 2 + nt2;
                    mma_bf16(Co[nt], phi, &vbh[nt2 * 2]);
                    mma_bf16(Co[nt], plo, &vbh[nt2 * 2]);
                    mma_bf16(Co[nt], phi, &vbl[nt2 * 2]);
                }
            }
        }
        __syncthreads();
    }

    l0 += __shfl_xor_sync(0xffffffffu, l0, 1);
    l0 += __shfl_xor_sync(0xffffffffu, l0, 2);
    l1 += __shfl_xor_sync(0xffffffffu, l1, 1);
    l1 += __shfl_xor_sync(0xffffffffu, l1, 2);
    float inv0 = 1.f / l0, inv1 = 1.f / l1;

    const int s0 = qt * 128 + wid * 16 + (lane >> 2);
    #pragma unroll
    for (int nt = 0; nt < 8; nt++) {
        int col = h * HD_ + nt * 8 + (lane & 3) * 2;
        size_t o0 = (size_t)(b * S_ + s0) * H_ + col;
        size_t o1 = (size_t)(b * S_ + s0 + 8) * H_ + col;
        uint32_t hi, lo;
        pack_split(Co[nt][0] * inv0, Co[nt][1] * inv0, hi, lo);
        *(uint32_t*)&g_Chi[o0] = hi;
        *(uint32_t*)&g_Clo[o0] = lo;
        pack_split(Co[nt][2] * inv1, Co[nt][3] * inv1, hi, lo);
        *(uint32_t*)&g_Chi[o1] = hi;
        *(uint32_t*)&g_Clo[o1] = lo;
    }
}

// ---------------------------------------------------------------------------
// LayerNorm
// ---------------------------------------------------------------------------
__global__ __launch_bounds__(256) void ln_kernel(
    const float* __restrict__ gamma, const float* __restrict__ beta,
    float* __restrict__ out)
{
    const int row = blockIdx.x;
    const int tid = threadIdx.x;
    const float* x = g_x + (size_t)row * H_;

    float4 v = *(const float4*)&x[tid * 4];
    float s  = v.x + v.y + v.z + v.w;
    float ss = v.x * v.x + v.y * v.y + v.z * v.z + v.w * v.w;

    #pragma unroll
    for (int o = 16; o > 0; o >>= 1) {
        s  += __shfl_xor_sync(0xffffffffu, s,  o);
        ss += __shfl_xor_sync(0xffffffffu, ss, o);
    }
    __shared__ float rs[8], rss[8];
    int wid = tid >> 5, lid = tid & 31;
    if (lid == 0) { rs[wid] = s; rss[wid] = ss; }
    __syncthreads();
    if (wid == 0) {
        float a = (lid < 8) ? rs[lid]  : 0.f;
        float c = (lid < 8) ? rss[lid] : 0.f;
        #pragma unroll
        for (int o = 4; o > 0; o >>= 1) {
            a += __shfl_xor_sync(0xffffffffu, a, o);
            c += __shfl_xor_sync(0xffffffffu, c, o);
        }
        if (lid == 0) { rs[0] = a; rss[0] = c; }
    }
    __syncthreads();

    float mean = rs[0] * (1.f / H_);
    float var  = rss[0] * (1.f / H_) - mean * mean;
    float rstd = rsqrtf(var + LN_EPS);

    float4 g = *(const float4*)&gamma[tid * 4];
    float4 bt = *(const float4*)&beta[tid * 4];
    float4 y;
    y.x = (v.x - mean) * rstd * g.x + bt.x;
    y.y = (v.y - mean) * rstd * g.y + bt.y;
    y.z = (v.z - mean) * rstd * g.z + bt.z;
    y.w = (v.w - mean) * rstd * g.w + bt.w;
    *(float4*)&out[(size_t)row * H_ + tid * 4] = y;
}

// ---------------------------------------------------------------------------
extern "C" void kernel_launch(void* const* d_in, const int* in_sizes, int n_in,
                              void* d_out, int out_size)
{
    const float* hidden = (const float*)d_in[0];
    const float* mask   = (const float*)d_in[1];
    const float* Wq     = (const float*)d_in[2];
    const float* bq     = (const float*)d_in[3];
    const float* Wk     = (const float*)d_in[4];
    const float* bk     = (const float*)d_in[5];
    const float* Wv     = (const float*)d_in[6];
    const float* bv     = (const float*)d_in[7];
    const float* Wo     = (const float*)d_in[8];
    const float* bo     = (const float*)d_in[9];
    const float* gamma  = (const float*)d_in[10];
    const float* beta   = (const float*)d_in[11];
    float* out          = (float*)d_out;

    static int attr_set = 0;
    if (!attr_set) {
        cudaFuncSetAttribute(gemm_kernel, cudaFuncAttributeMaxDynamicSharedMemorySize, GEMM_SMEM);
        attr_set = 1;
    }

    unsigned short *xhi, *xlo, *whi, *wlo, *chi, *clo;
    cudaGetSymbolAddress((void**)&xhi, g_Xhi);
    cudaGetSymbolAddress((void**)&xlo, g_Xlo);
    cudaGetSymbolAddress((void**)&whi, g_Whi);
    cudaGetSymbolAddress((void**)&wlo, g_Wlo);
    cudaGetSymbolAddress((void**)&chi, g_Chi);
    cudaGetSymbolAddress((void**)&clo, g_Clo);

    const int NW = H_ * H_ / 4;
    split_kernel<<<(M_ * H_ / 4 + 255) / 256, 256>>>(hidden, xhi, xlo, M_ * H_ / 4);
    split_kernel<<<(NW + 255) / 256, 256>>>(Wq, whi + 0 * H_ * H_, wlo + 0 * H_ * H_, NW);
    split_kernel<<<(NW + 255) / 256, 256>>>(Wk, whi + 1 * H_ * H_, wlo + 1 * H_ * H_, NW);
    split_kernel<<<(NW + 255) / 256, 256>>>(Wv, whi + 2 * H_ * H_, wlo + 2 * H_ * H_, NW);
    split_kernel<<<(NW + 255) / 256, 256>>>(Wo, whi + 3 * H_ * H_, wlo + 3 * H_ * H_, NW);

    dim3 qkv_grid(H_ / 128, M_ / 128, 3);
    gemm_kernel<<<qkv_grid, 256, GEMM_SMEM>>>(xhi, xlo, 0, bq, bk, bv, nullptr);

    dim3 attn_grid(S_ / 128, B_ * NH_);
    attn_kernel<<<attn_grid, 256>>>(mask);

    dim3 out_grid(H_ / 128, M_ / 128, 1);
    gemm_kernel<<<out_grid, 256, GEMM_SMEM>>>(chi, clo, 3, bo, nullptr, nullptr, hidden);

    ln_kernel<<<M_, 256>>>(gamma, beta, out);
}

// round 8
// speedup vs baseline: 1.1329x; 1.1329x over previous
#include <cuda_runtime.h>
#include <cuda_bf16.h>
#include <math_constants.h>
#include <cstdint>

#define B_ 8
#define S_ 1024
#define H_ 1024
#define NH_ 16
#define HD_ 64
#define M_ (B_ * S_)        // 8192
#define LN_EPS 1e-12f

// fp32 scratch
__device__ float g_x[M_ * H_];    // residual-added pre-LN

// bf16 hi/lo split scratch (u16 bits)
__device__ unsigned short g_Xhi[M_ * H_];
__device__ unsigned short g_Xlo[M_ * H_];
__device__ unsigned short g_Whi[4 * H_ * H_];   // Wq,Wk,Wv,Wo
__device__ unsigned short g_Wlo[4 * H_ * H_];
__device__ unsigned short g_Qh[M_ * H_];        // [B*NH][S][HD]
__device__ unsigned short g_Ql[M_ * H_];
__device__ unsigned short g_Kh[M_ * H_];
__device__ unsigned short g_Kl[M_ * H_];
__device__ unsigned short g_Vh[M_ * H_];
__device__ unsigned short g_Vl[M_ * H_];
__device__ unsigned short g_Chi[M_ * H_];       // ctx split [B,S,H]
__device__ unsigned short g_Clo[M_ * H_];

// ---------------------------------------------------------------------------
// helpers (family-agnostic PTX: ldmatrix sm_75+, mma.sync bf16 + cp.async sm_80+)
// ---------------------------------------------------------------------------
__device__ __forceinline__ uint32_t smem_u32(const void* p) {
    uint32_t a;
    asm("{ .reg .u64 t; cvta.to.shared.u64 t, %1; cvt.u32.u64 %0, t; }" : "=r"(a) : "l"(p));
    return a;
}
__device__ __forceinline__ void ldm_x4(uint32_t& r0, uint32_t& r1, uint32_t& r2, uint32_t& r3,
                                       uint32_t addr) {
    asm volatile("ldmatrix.sync.aligned.m8n8.x4.shared.b16 {%0,%1,%2,%3}, [%4];"
                 : "=r"(r0), "=r"(r1), "=r"(r2), "=r"(r3) : "r"(addr));
}
__device__ __forceinline__ void ldm_x4_t(uint32_t& r0, uint32_t& r1, uint32_t& r2, uint32_t& r3,
                                         uint32_t addr) {
    asm volatile("ldmatrix.sync.aligned.m8n8.x4.trans.shared.b16 {%0,%1,%2,%3}, [%4];"
                 : "=r"(r0), "=r"(r1), "=r"(r2), "=r"(r3) : "r"(addr));
}
__device__ __forceinline__ void mma_bf16(float* d, const uint32_t* a, const uint32_t* b) {
    asm volatile(
        "mma.sync.aligned.m16n8k16.row.col.f32.bf16.bf16.f32 "
        "{%0,%1,%2,%3}, {%4,%5,%6,%7}, {%8,%9}, {%0,%1,%2,%3};"
        : "+f"(d[0]), "+f"(d[1]), "+f"(d[2]), "+f"(d[3])
        : "r"(a[0]), "r"(a[1]), "r"(a[2]), "r"(a[3]), "r"(b[0]), "r"(b[1]));
}
__device__ __forceinline__ void cp16(uint32_t dst, const void* src) {
    asm volatile("cp.async.cg.shared.global [%0], [%1], 16;" :: "r"(dst), "l"(src));
}
__device__ __forceinline__ void cp_commit() { asm volatile("cp.async.commit_group;"); }
// split two fp32 into packed bf16x2 hi + bf16x2 lo
__device__ __forceinline__ void pack_split(float a, float b, uint32_t& hi, uint32_t& lo) {
    __nv_bfloat16 ha = __float2bfloat16(a), hb = __float2bfloat16(b);
    __nv_bfloat16 la = __float2bfloat16(a - __bfloat162float(ha));
    __nv_bfloat16 lb = __float2bfloat16(b - __bfloat162float(hb));
    hi = (uint32_t)__bfloat16_as_ushort(ha) | ((uint32_t)__bfloat16_as_ushort(hb) << 16);
    lo = (uint32_t)__bfloat16_as_ushort(la) | ((uint32_t)__bfloat16_as_ushort(lb) << 16);
}

// ---------------------------------------------------------------------------
// split fp32 -> bf16 hi + bf16 lo (X and weights)
// ---------------------------------------------------------------------------
__global__ __launch_bounds__(256) void split_kernel(
    const float* __restrict__ src, unsigned short* __restrict__ hi,
    unsigned short* __restrict__ lo, int n4)
{
    int i = blockIdx.x * 256 + threadIdx.x;
    if (i >= n4) return;
    float4 v = ((const float4*)src)[i];
    float f[4] = {v.x, v.y, v.z, v.w};
    ushort4 hh, ll;
    unsigned short* hp = &hh.x;
    unsigned short* lp = &ll.x;
    #pragma unroll
    for (int j = 0; j < 4; j++) {
        __nv_bfloat16 h = __float2bfloat16(f[j]);
        float r = f[j] - __bfloat162float(h);
        __nv_bfloat16 l = __float2bfloat16(r);
        hp[j] = __bfloat16_as_ushort(h);
        lp[j] = __bfloat16_as_ushort(l);
    }
    ((ushort4*)hi)[i] = hh;
    ((ushort4*)lo)[i] = ll;
}

// ---------------------------------------------------------------------------
// cp.async 2-stage split-bf16 GEMM: C[m][n] = sum_k A[m][k]*W[n][k]
// BM=128 BN=128 BK=32, 256 thr (8 warps 4x2), warp tile 32x64, 3 mma passes.
// 80 KB smem -> 2 CTAs/SM with launch_bounds(256,2).
// ---------------------------------------------------------------------------
#define BK 32
#define NCH (H_ / BK)        // 32
#define STR 40               // smem row stride (halves)
#define MAT_H (128 * STR)
#define STG_H (4 * MAT_H)
#define GEMM_SMEM (2 * STG_H * 2)   // 81920 B

__global__ __launch_bounds__(256, 2) void gemm_kernel(
    const unsigned short* __restrict__ Ahi, const unsigned short* __restrict__ Alo,
    int wbase,
    const float* __restrict__ bias0, const float* __restrict__ bias1,
    const float* __restrict__ bias2, const float* __restrict__ residual)
{
    extern __shared__ unsigned short sm[];
    const uint32_t sbase = smem_u32(sm);

    const int tid = threadIdx.x;
    const int wid = tid >> 5;
    const int lane = tid & 31;
    const int warp_m = wid & 3;
    const int warp_n = wid >> 2;
    const int w  = wbase + blockIdx.z;
    const int n0 = blockIdx.x * 128;
    const int m0 = blockIdx.y * 128;

    const unsigned short* Bhi = g_Whi + ((size_t)w << 20);
    const unsigned short* Blo = g_Wlo + ((size_t)w << 20);
    const float* bias = (w == 1) ? bias1 : (w == 2) ? bias2 : bias0;

    const unsigned short* gsrc[4] = {Ahi, Alo, Bhi, Blo};
    const int gbase[4] = {m0, m0, n0, n0};

    auto issue_stage = [&](int c) {
        const int st = c & 1;
        const int kc = c * BK;
        #pragma unroll
        for (int t = 0; t < 8; t++) {
            int v = tid + t * 256;
            int mat = v >> 9;
            int rem = v & 511;
            int row = rem >> 2;
            int g = (rem & 3) * 8;
            const unsigned short* src = gsrc[mat] + (size_t)(gbase[mat] + row) * H_ + kc + g;
            uint32_t dst = sbase + (uint32_t)(st * STG_H + mat * MAT_H + row * STR + g) * 2;
            cp16(dst, src);
        }
        cp_commit();
    };

    float C[2][8][4];
    #pragma unroll
    for (int a = 0; a < 2; a++)
        #pragma unroll
        for (int b = 0; b < 8; b++)
            #pragma unroll
            for (int c = 0; c < 4; c++) C[a][b][c] = 0.f;

    issue_stage(0);

    for (int c = 0; c < NCH; c++) {
        // issue next stage into the buffer freed at the end of iter c-1
        if (c + 1 < NCH) {
            issue_stage(c + 1);
            asm volatile("cp.async.wait_group 1;" ::: "memory");
        } else {
            asm volatile("cp.async.wait_group 0;" ::: "memory");
        }
        __syncthreads();

        const uint32_t stage = sbase + (uint32_t)(c & 1) * (STG_H * 2);

        #pragma unroll
        for (int ks = 0; ks < 2; ks++) {
            const int k0 = ks * 16;
            uint32_t ah[2][4], al[2][4];
            #pragma unroll
            for (int mt = 0; mt < 2; mt++) {
                int row = warp_m * 32 + mt * 16 + (lane & 15);
                int col = k0 + (lane >> 4) * 8;
                uint32_t off = (uint32_t)(row * STR + col) * 2;
                ldm_x4(ah[mt][0], ah[mt][1], ah[mt][2], ah[mt][3],
                       stage + 0 * MAT_H * 2 + off);
                ldm_x4(al[mt][0], al[mt][1], al[mt][2], al[mt][3],
                       stage + 1 * MAT_H * 2 + off);
            }
            #pragma unroll
            for (int ntp = 0; ntp < 4; ntp++) {
                int brow = warp_n * 64 + ntp * 16 + (lane & 7) + (lane >> 4) * 8;
                int bcol = k0 + ((lane >> 3) & 1) * 8;
                uint32_t off = (uint32_t)(brow * STR + bcol) * 2;
                uint32_t bh[4], bl[4];
                ldm_x4(bh[0], bh[1], bh[2], bh[3], stage + 2 * MAT_H * 2 + off);
                ldm_x4(bl[0], bl[1], bl[2], bl[3], stage + 3 * MAT_H * 2 + off);
                #pragma unroll
                for (int nt2 = 0; nt2 < 2; nt2++) {
                    const int nt = ntp * 2 + nt2;
                    #pragma unroll
                    for (int mt = 0; mt < 2; mt++) {
                        mma_bf16(C[mt][nt], ah[mt], &bh[nt2 * 2]);
                        mma_bf16(C[mt][nt], ah[mt], &bl[nt2 * 2]);
                        mma_bf16(C[mt][nt], al[mt], &bh[nt2 * 2]);
                    }
                }
            }
        }
        __syncthreads();
    }

    // epilogue
    unsigned short* oh = (w == 0) ? g_Qh : (w == 1) ? g_Kh : g_Vh;
    unsigned short* ol = (w == 0) ? g_Ql : (w == 1) ? g_Kl : g_Vl;
    #pragma unroll
    for (int mt = 0; mt < 2; mt++) {
        #pragma unroll
        for (int nt = 0; nt < 8; nt++) {
            const float* d = C[mt][nt];
            int m = m0 + warp_m * 32 + mt * 16 + (lane >> 2);
            int n = n0 + warp_n * 64 + nt * 8 + (lane & 3) * 2;
            float b0 = bias[n], b1 = bias[n + 1];
            if (w < 3) {
                int h = n >> 6, dd = n & 63;
                #pragma unroll
                for (int rr = 0; rr < 2; rr++) {
                    int mm = m + rr * 8;
                    int bb = mm >> 10, ss = mm & 1023;
                    size_t o = ((size_t)(bb * NH_ + h) * S_ + ss) * HD_ + dd;
                    uint32_t hi, lo;
                    pack_split(d[rr * 2 + 0] + b0, d[rr * 2 + 1] + b1, hi, lo);
                    *(uint32_t*)&oh[o] = hi;
                    *(uint32_t*)&ol[o] = lo;
                }
            } else {
                #pragma unroll
                for (int rr = 0; rr < 2; rr++) {
                    int mm = m + rr * 8;
                    size_t idx = (size_t)mm * H_ + n;
                    float2 res = *(const float2*)&residual[idx];
                    float2 o = make_float2(d[rr * 2 + 0] + b0 + res.x,
                                           d[rr * 2 + 1] + b1 + res.y);
                    *(float2*)&g_x[idx] = o;
                }
            }
        }
    }
}

// ---------------------------------------------------------------------------
// Tensor-core flash attention, split-bf16, fp32 softmax.
// grid (S/128=8, B*NH=128), 256 thr (8 warps, 16 q-rows each).
// ---------------------------------------------------------------------------
#define ASTR 72   // smem row stride (u16)

__global__ __launch_bounds__(256) void attn_kernel(const float* __restrict__ mask)
{
    __shared__ unsigned short Kh[64 * ASTR], Kl[64 * ASTR];
    __shared__ unsigned short Vh[64 * ASTR], Vl[64 * ASTR];
    __shared__ float msk[S_];

    const int bh  = blockIdx.y;
    const int qt  = blockIdx.x;
    const int tid = threadIdx.x;
    const int wid = tid >> 5;
    const int lane = tid & 31;
    const int b   = bh >> 4;
    const int h   = bh & 15;
    const size_t base = (size_t)bh * S_ * HD_;

    const uint32_t sKh = smem_u32(Kh), sKl = smem_u32(Kl);
    const uint32_t sVh = smem_u32(Vh), sVl = smem_u32(Vl);

    // mask row -> smem (1024 floats, 256 threads)
    ((float4*)msk)[tid] = ((const float4*)(mask + (size_t)b * S_))[tid];

    // stage Q (128 rows): hi -> Kh(0-63)/Vh(64-127), lo -> Kl/Vl
    #pragma unroll
    for (int t = 0; t < 4; t++) {
        int idx = tid + t * 256;            // 0..1023
        int row = idx >> 3, g = (idx & 7) * 8;
        size_t go = base + (size_t)(qt * 128 + row) * HD_ + g;
        unsigned short* dh = (row < 64) ? Kh : Vh;
        unsigned short* dl = (row < 64) ? Kl : Vl;
        int r = row & 63;
        *(uint4*)&dh[r * ASTR + g] = *(const uint4*)&g_Qh[go];
        *(uint4*)&dl[r * ASTR + g] = *(const uint4*)&g_Ql[go];
    }
    __syncthreads();

    uint32_t qh[4][4], ql[4][4];
    {
        const uint32_t bh_ = (wid < 4) ? sKh : sVh;
        const uint32_t bl_ = (wid < 4) ? sKl : sVl;
        int rbase = (wid & 3) * 16 + (lane & 15);
        #pragma unroll
        for (int ks = 0; ks < 4; ks++) {
            int col = ks * 16 + (lane >> 4) * 8;
            uint32_t off = (uint32_t)(rbase * ASTR + col) * 2;
            ldm_x4(qh[ks][0], qh[ks][1], qh[ks][2], qh[ks][3], bh_ + off);
            ldm_x4(ql[ks][0], ql[ks][1], ql[ks][2], ql[ks][3], bl_ + off);
        }
    }
    __syncthreads();

    float Co[8][4];
    #pragma unroll
    for (int i = 0; i < 8; i++)
        #pragma unroll
        for (int j = 0; j < 4; j++) Co[i][j] = 0.f;
    float m0 = -CUDART_INF_F, m1 = -CUDART_INF_F, l0 = 0.f, l1 = 0.f;

    for (int kt = 0; kt < S_ / 64; kt++) {
        // load K/V hi+lo tiles (64 rows each)
        #pragma unroll
        for (int t = 0; t < 2; t++) {
            int idx = tid + t * 256;        // 0..511
            int row = idx >> 3, g = (idx & 7) * 8;
            size_t go = base + (size_t)(kt * 64 + row) * HD_ + g;
            *(uint4*)&Kh[row * ASTR + g] = *(const uint4*)&g_Kh[go];
            *(uint4*)&Kl[row * ASTR + g] = *(const uint4*)&g_Kl[go];
            *(uint4*)&Vh[row * ASTR + g] = *(const uint4*)&g_Vh[go];
            *(uint4*)&Vl[row * ASTR + g] = *(const uint4*)&g_Vl[go];
        }
        __syncthreads();

        // S = Q K^T (3 split passes)
        float Cs[8][4];
        #pragma unroll
        for (int i = 0; i < 8; i++)
            #pragma unroll
            for (int j = 0; j < 4; j++) Cs[i][j] = 0.f;

        #pragma unroll
        for (int ks = 0; ks < 4; ks++) {
            #pragma unroll
            for (int ntp = 0; ntp < 4; ntp++) {
                int brow = ntp * 16 + (lane & 7) + (lane >> 4) * 8;
                int bcol = ks * 16 + ((lane >> 3) & 1) * 8;
                uint32_t off = (uint32_t)(brow * ASTR + bcol) * 2;
                uint32_t kbh[4], kbl[4];
                ldm_x4(kbh[0], kbh[1], kbh[2], kbh[3], sKh + off);
                ldm_x4(kbl[0], kbl[1], kbl[2], kbl[3], sKl + off);
                #pragma unroll
                for (int nt2 = 0; nt2 < 2; nt2++) {
                    const int nt = ntp * 2 + nt2;
                    mma_bf16(Cs[nt], qh[ks], &kbh[nt2 * 2]);
                    mma_bf16(Cs[nt], qh[ks], &kbl[nt2 * 2]);
                    mma_bf16(Cs[nt], ql[ks], &kbh[nt2 * 2]);
                }
            }
        }

        // scale + mask + online softmax
        float mn0 = m0, mn1 = m1;
        #pragma unroll
        for (int nt = 0; nt < 8; nt++) {
            int col = kt * 64 + nt * 8 + (lane & 3) * 2;
            float mka = msk[col], mkb = msk[col + 1];
            Cs[nt][0] = fmaf(Cs[nt][0], 0.125f, mka);
            Cs[nt][1] = fmaf(Cs[nt][1], 0.125f, mkb);
            Cs[nt][2] = fmaf(Cs[nt][2], 0.125f, mka);
            Cs[nt][3] = fmaf(Cs[nt][3], 0.125f, mkb);
            mn0 = fmaxf(mn0, fmaxf(Cs[nt][0], Cs[nt][1]));
            mn1 = fmaxf(mn1, fmaxf(Cs[nt][2], Cs[nt][3]));
        }
        mn0 = fmaxf(mn0, __shfl_xor_sync(0xffffffffu, mn0, 1));
        mn0 = fmaxf(mn0, __shfl_xor_sync(0xffffffffu, mn0, 2));
        mn1 = fmaxf(mn1, __shfl_xor_sync(0xffffffffu, mn1, 1));
        mn1 = fmaxf(mn1, __shfl_xor_sync(0xffffffffu, mn1, 2));

        float f0 = __expf(m0 - mn0), f1 = __expf(m1 - mn1);
        m0 = mn0; m1 = mn1;
        l0 *= f0; l1 *= f1;
        #pragma unroll
        for (int nt = 0; nt < 8; nt++) {
            Co[nt][0] *= f0; Co[nt][1] *= f0;
            Co[nt][2] *= f1; Co[nt][3] *= f1;
        }
        #pragma unroll
        for (int nt = 0; nt < 8; nt++) {
            Cs[nt][0] = __expf(Cs[nt][0] - m0);
            Cs[nt][1] = __expf(Cs[nt][1] - m0);
            Cs[nt][2] = __expf(Cs[nt][2] - m1);
            Cs[nt][3] = __expf(Cs[nt][3] - m1);
            l0 += Cs[nt][0] + Cs[nt][1];
            l1 += Cs[nt][2] + Cs[nt][3];
        }

        // O += P V (3 split passes)
        #pragma unroll
        for (int kc = 0; kc < 4; kc++) {
            uint32_t phi[4], plo[4];
            pack_split(Cs[2 * kc][0],     Cs[2 * kc][1],     phi[0], plo[0]);
            pack_split(Cs[2 * kc][2],     Cs[2 * kc][3],     phi[1], plo[1]);
            pack_split(Cs[2 * kc + 1][0], Cs[2 * kc + 1][1], phi[2], plo[2]);
            pack_split(Cs[2 * kc + 1][2], Cs[2 * kc + 1][3], phi[3], plo[3]);
            #pragma unroll
            for (int ntp = 0; ntp < 4; ntp++) {
                uint32_t off = (uint32_t)((kc * 16 + (lane & 15)) * ASTR +
                                          ntp * 16 + (lane >> 4) * 8) * 2;
                uint32_t vbh[4], vbl[4];
                ldm_x4_t(vbh[0], vbh[1], vbh[2], vbh[3], sVh + off);
                ldm_x4_t(vbl[0], vbl[1], vbl[2], vbl[3], sVl + off);
                #pragma unroll
                for (int nt2 = 0; nt2 < 2; nt2++) {
                    const int nt = ntp * 2 + nt2;
                    mma_bf16(Co[nt], phi, &vbh[nt2 * 2]);
                    mma_bf16(Co[nt], plo, &vbh[nt2 * 2]);
                    mma_bf16(Co[nt], phi, &vbl[nt2 * 2]);
                }
            }
        }
        __syncthreads();
    }

    l0 += __shfl_xor_sync(0xffffffffu, l0, 1);
    l0 += __shfl_xor_sync(0xffffffffu, l0, 2);
    l1 += __shfl_xor_sync(0xffffffffu, l1, 1);
    l1 += __shfl_xor_sync(0xffffffffu, l1, 2);
    float inv0 = 1.f / l0, inv1 = 1.f / l1;

    const int s0 = qt * 128 + wid * 16 + (lane >> 2);
    #pragma unroll
    for (int nt = 0; nt < 8; nt++) {
        int col = h * HD_ + nt * 8 + (lane & 3) * 2;
        size_t o0 = (size_t)(b * S_ + s0) * H_ + col;
        size_t o1 = (size_t)(b * S_ + s0 + 8) * H_ + col;
        uint32_t hi, lo;
        pack_split(Co[nt][0] * inv0, Co[nt][1] * inv0, hi, lo);
        *(uint32_t*)&g_Chi[o0] = hi;
        *(uint32_t*)&g_Clo[o0] = lo;
        pack_split(Co[nt][2] * inv1, Co[nt][3] * inv1, hi, lo);
        *(uint32_t*)&g_Chi[o1] = hi;
        *(uint32_t*)&g_Clo[o1] = lo;
    }
}

// ---------------------------------------------------------------------------
// LayerNorm
// ---------------------------------------------------------------------------
__global__ __launch_bounds__(256) void ln_kernel(
    const float* __restrict__ gamma, const float* __restrict__ beta,
    float* __restrict__ out)
{
    const int row = blockIdx.x;
    const int tid = threadIdx.x;
    const float* x = g_x + (size_t)row * H_;

    float4 v = *(const float4*)&x[tid * 4];
    float s  = v.x + v.y + v.z + v.w;
    float ss = v.x * v.x + v.y * v.y + v.z * v.z + v.w * v.w;

    #pragma unroll
    for (int o = 16; o > 0; o >>= 1) {
        s  += __shfl_xor_sync(0xffffffffu, s,  o);
        ss += __shfl_xor_sync(0xffffffffu, ss, o);
    }
    __shared__ float rs[8], rss[8];
    int wid = tid >> 5, lid = tid & 31;
    if (lid == 0) { rs[wid] = s; rss[wid] = ss; }
    __syncthreads();
    if (wid == 0) {
        float a = (lid < 8) ? rs[lid]  : 0.f;
        float c = (lid < 8) ? rss[lid] : 0.f;
        #pragma unroll
        for (int o = 4; o > 0; o >>= 1) {
            a += __shfl_xor_sync(0xffffffffu, a, o);
            c += __shfl_xor_sync(0xffffffffu, c, o);
        }
        if (lid == 0) { rs[0] = a; rss[0] = c; }
    }
    __syncthreads();

    float mean = rs[0] * (1.f / H_);
    float var  = rss[0] * (1.f / H_) - mean * mean;
    float rstd = rsqrtf(var + LN_EPS);

    float4 g = *(const float4*)&gamma[tid * 4];
    float4 bt = *(const float4*)&beta[tid * 4];
    float4 y;
    y.x = (v.x - mean) * rstd * g.x + bt.x;
    y.y = (v.y - mean) * rstd * g.y + bt.y;
    y.z = (v.z - mean) * rstd * g.z + bt.z;
    y.w = (v.w - mean) * rstd * g.w + bt.w;
    *(float4*)&out[(size_t)row * H_ + tid * 4] = y;
}

// ---------------------------------------------------------------------------
extern "C" void kernel_launch(void* const* d_in, const int* in_sizes, int n_in,
                              void* d_out, int out_size)
{
    const float* hidden = (const float*)d_in[0];
    const float* mask   = (const float*)d_in[1];
    const float* Wq     = (const float*)d_in[2];
    const float* bq     = (const float*)d_in[3];
    const float* Wk     = (const float*)d_in[4];
    const float* bk     = (const float*)d_in[5];
    const float* Wv     = (const float*)d_in[6];
    const float* bv     = (const float*)d_in[7];
    const float* Wo     = (const float*)d_in[8];
    const float* bo     = (const float*)d_in[9];
    const float* gamma  = (const float*)d_in[10];
    const float* beta   = (const float*)d_in[11];
    float* out          = (float*)d_out;

    static int attr_set = 0;
    if (!attr_set) {
        cudaFuncSetAttribute(gemm_kernel, cudaFuncAttributeMaxDynamicSharedMemorySize, GEMM_SMEM);
        attr_set = 1;
    }

    unsigned short *xhi, *xlo, *whi, *wlo, *chi, *clo;
    cudaGetSymbolAddress((void**)&xhi, g_Xhi);
    cudaGetSymbolAddress((void**)&xlo, g_Xlo);
    cudaGetSymbolAddress((void**)&whi, g_Whi);
    cudaGetSymbolAddress((void**)&wlo, g_Wlo);
    cudaGetSymbolAddress((void**)&chi, g_Chi);
    cudaGetSymbolAddress((void**)&clo, g_Clo);

    const int NW = H_ * H_ / 4;
    split_kernel<<<(M_ * H_ / 4 + 255) / 256, 256>>>(hidden, xhi, xlo, M_ * H_ / 4);
    split_kernel<<<(NW + 255) / 256, 256>>>(Wq, whi + 0 * H_ * H_, wlo + 0 * H_ * H_, NW);
    split_kernel<<<(NW + 255) / 256, 256>>>(Wk, whi + 1 * H_ * H_, wlo + 1 * H_ * H_, NW);
    split_kernel<<<(NW + 255) / 256, 256>>>(Wv, whi + 2 * H_ * H_, wlo + 2 * H_ * H_, NW);
    split_kernel<<<(NW + 255) / 256, 256>>>(Wo, whi + 3 * H_ * H_, wlo + 3 * H_ * H_, NW);

    dim3 qkv_grid(H_ / 128, M_ / 128, 3);
    gemm_kernel<<<qkv_grid, 256, GEMM_SMEM>>>(xhi, xlo, 0, bq, bk, bv, nullptr);

    dim3 attn_grid(S_ / 128, B_ * NH_);
    attn_kernel<<<attn_grid, 256>>>(mask);

    dim3 out_grid(H_ / 128, M_ / 128, 1);
    gemm_kernel<<<out_grid, 256, GEMM_SMEM>>>(chi, clo, 3, bo, nullptr, nullptr, hidden);

    ln_kernel<<<M_, 256>>>(gamma, beta, out);
}

// round 9
// speedup vs baseline: 1.5792x; 1.3939x over previous
#include <cuda_runtime.h>
#include <cuda_fp16.h>
#include <math_constants.h>
#include <cstdint>

#define B_ 8
#define S_ 1024
#define H_ 1024
#define NH_ 16
#define HD_ 64
#define M_ (B_ * S_)        // 8192
#define LN_EPS 1e-12f

// fp32 scratch
__device__ float g_x[M_ * H_];    // residual-added pre-LN

// fp16 hi/lo split scratch (u16 bits). A-side operands need hi only.
__device__ unsigned short g_Xhi[M_ * H_];
__device__ unsigned short g_Whi[4 * H_ * H_];   // Wq,Wk,Wv,Wo
__device__ unsigned short g_Wlo[4 * H_ * H_];
__device__ unsigned short g_Qh[M_ * H_];        // [B*NH][S][HD]
__device__ unsigned short g_Kh[M_ * H_];
__device__ unsigned short g_Kl[M_ * H_];
__device__ unsigned short g_Vh[M_ * H_];
__device__ unsigned short g_Vl[M_ * H_];
__device__ unsigned short g_Chi[M_ * H_];       // ctx fp16 [B,S,H]

// ---------------------------------------------------------------------------
// helpers (family-agnostic PTX: ldmatrix sm_75+, mma.sync f16 + cp.async sm_80+)
// ---------------------------------------------------------------------------
__device__ __forceinline__ uint32_t smem_u32(const void* p) {
    uint32_t a;
    asm("{ .reg .u64 t; cvta.to.shared.u64 t, %1; cvt.u32.u64 %0, t; }" : "=r"(a) : "l"(p));
    return a;
}
__device__ __forceinline__ void ldm_x4(uint32_t& r0, uint32_t& r1, uint32_t& r2, uint32_t& r3,
                                       uint32_t addr) {
    asm volatile("ldmatrix.sync.aligned.m8n8.x4.shared.b16 {%0,%1,%2,%3}, [%4];"
                 : "=r"(r0), "=r"(r1), "=r"(r2), "=r"(r3) : "r"(addr));
}
__device__ __forceinline__ void ldm_x4_t(uint32_t& r0, uint32_t& r1, uint32_t& r2, uint32_t& r3,
                                         uint32_t addr) {
    asm volatile("ldmatrix.sync.aligned.m8n8.x4.trans.shared.b16 {%0,%1,%2,%3}, [%4];"
                 : "=r"(r0), "=r"(r1), "=r"(r2), "=r"(r3) : "r"(addr));
}
__device__ __forceinline__ void mma_f16(float* d, const uint32_t* a, const uint32_t* b) {
    asm volatile(
        "mma.sync.aligned.m16n8k16.row.col.f32.f16.f16.f32 "
        "{%0,%1,%2,%3}, {%4,%5,%6,%7}, {%8,%9}, {%0,%1,%2,%3};"
        : "+f"(d[0]), "+f"(d[1]), "+f"(d[2]), "+f"(d[3])
        : "r"(a[0]), "r"(a[1]), "r"(a[2]), "r"(a[3]), "r"(b[0]), "r"(b[1]));
}
__device__ __forceinline__ void cp16(uint32_t dst, const void* src) {
    asm volatile("cp.async.cg.shared.global [%0], [%1], 16;" :: "r"(dst), "l"(src));
}
__device__ __forceinline__ void cp_commit() { asm volatile("cp.async.commit_group;"); }

__device__ __forceinline__ uint32_t pack2_f16(float a, float b) {
    __half ha = __float2half(a), hb = __float2half(b);
    return (uint32_t)__half_as_ushort(ha) | ((uint32_t)__half_as_ushort(hb) << 16);
}
__device__ __forceinline__ void pack_split_f16(float a, float b, uint32_t& hi, uint32_t& lo) {
    __half ha = __float2half(a), hb = __float2half(b);
    __half la = __float2half(a - __half2float(ha));
    __half lb = __float2half(b - __half2float(hb));
    hi = (uint32_t)__half_as_ushort(ha) | ((uint32_t)__half_as_ushort(hb) << 16);
    lo = (uint32_t)__half_as_ushort(la) | ((uint32_t)__half_as_ushort(lb) << 16);
}

// ---------------------------------------------------------------------------
// splits: fp32 -> fp16 hi (A operands) / hi+lo (weights)
// ---------------------------------------------------------------------------
__global__ __launch_bounds__(256) void split_hi_kernel(
    const float* __restrict__ src, unsigned short* __restrict__ hi, int n4)
{
    int i = blockIdx.x * 256 + threadIdx.x;
    if (i >= n4) return;
    float4 v = ((const float4*)src)[i];
    ushort4 hh;
    hh.x = __half_as_ushort(__float2half(v.x));
    hh.y = __half_as_ushort(__float2half(v.y));
    hh.z = __half_as_ushort(__float2half(v.z));
    hh.w = __half_as_ushort(__float2half(v.w));
    ((ushort4*)hi)[i] = hh;
}

__global__ __launch_bounds__(256) void split_hilo_kernel(
    const float* __restrict__ src, unsigned short* __restrict__ hi,
    unsigned short* __restrict__ lo, int n4)
{
    int i = blockIdx.x * 256 + threadIdx.x;
    if (i >= n4) return;
    float4 v = ((const float4*)src)[i];
    float f[4] = {v.x, v.y, v.z, v.w};
    ushort4 hh, ll;
    unsigned short* hp = &hh.x;
    unsigned short* lp = &ll.x;
    #pragma unroll
    for (int j = 0; j < 4; j++) {
        __half h = __float2half(f[j]);
        __half l = __float2half(f[j] - __half2float(h));
        hp[j] = __half_as_ushort(h);
        lp[j] = __half_as_ushort(l);
    }
    ((ushort4*)hi)[i] = hh;
    ((ushort4*)lo)[i] = ll;
}

// ---------------------------------------------------------------------------
// cp.async 2-stage split-fp16 GEMM: C[m][n] = sum_k A[m][k]*W[n][k]
// BM=128 BN=128 BK=32, 256 thr (8 warps 4x2), warp tile 32x64.
// 2 mma passes: Ah*Bh + Ah*Bl. Stage = 3 matrices (Ah,Bh,Bl) = 30 KB.
// ---------------------------------------------------------------------------
#define BK 32
#define NCH (H_ / BK)        // 32
#define STR 40               // smem row stride (halves)
#define MAT_H (128 * STR)
#define STG_H (3 * MAT_H)
#define GEMM_SMEM (2 * STG_H * 2)   // 61440 B

__global__ __launch_bounds__(256, 2) void gemm_kernel(
    const unsigned short* __restrict__ Ahi,
    int wbase,
    const float* __restrict__ bias0, const float* __restrict__ bias1,
    const float* __restrict__ bias2, const float* __restrict__ residual)
{
    extern __shared__ unsigned short sm[];
    const uint32_t sbase = smem_u32(sm);

    const int tid = threadIdx.x;
    const int wid = tid >> 5;
    const int lane = tid & 31;
    const int warp_m = wid & 3;
    const int warp_n = wid >> 2;
    const int w  = wbase + blockIdx.z;
    const int n0 = blockIdx.x * 128;
    const int m0 = blockIdx.y * 128;

    const unsigned short* Bhi = g_Whi + ((size_t)w << 20);
    const unsigned short* Blo = g_Wlo + ((size_t)w << 20);
    const float* bias = (w == 1) ? bias1 : (w == 2) ? bias2 : bias0;

    const unsigned short* gsrc[3] = {Ahi, Bhi, Blo};
    const int gbase[3] = {m0, n0, n0};

    auto issue_stage = [&](int c) {
        const int st = c & 1;
        const int kc = c * BK;
        #pragma unroll
        for (int t = 0; t < 6; t++) {
            int v = tid + t * 256;          // 0..1535
            int mat = v >> 9;
            int rem = v & 511;
            int row = rem >> 2;
            int g = (rem & 3) * 8;
            const unsigned short* src = gsrc[mat] + (size_t)(gbase[mat] + row) * H_ + kc + g;
            uint32_t dst = sbase + (uint32_t)(st * STG_H + mat * MAT_H + row * STR + g) * 2;
            cp16(dst, src);
        }
        cp_commit();
    };

    float C[2][8][4];
    #pragma unroll
    for (int a = 0; a < 2; a++)
        #pragma unroll
        for (int b = 0; b < 8; b++)
            #pragma unroll
            for (int c = 0; c < 4; c++) C[a][b][c] = 0.f;

    issue_stage(0);

    for (int c = 0; c < NCH; c++) {
        if (c + 1 < NCH) {
            issue_stage(c + 1);
            asm volatile("cp.async.wait_group 1;" ::: "memory");
        } else {
            asm volatile("cp.async.wait_group 0;" ::: "memory");
        }
        __syncthreads();

        const uint32_t stage = sbase + (uint32_t)(c & 1) * (STG_H * 2);

        #pragma unroll
        for (int ks = 0; ks < 2; ks++) {
            const int k0 = ks * 16;
            uint32_t ah[2][4];
            #pragma unroll
            for (int mt = 0; mt < 2; mt++) {
                int row = warp_m * 32 + mt * 16 + (lane & 15);
                int col = k0 + (lane >> 4) * 8;
                uint32_t off = (uint32_t)(row * STR + col) * 2;
                ldm_x4(ah[mt][0], ah[mt][1], ah[mt][2], ah[mt][3],
                       stage + 0 * MAT_H * 2 + off);
            }
            #pragma unroll
            for (int ntp = 0; ntp < 4; ntp++) {
                int brow = warp_n * 64 + ntp * 16 + (lane & 7) + (lane >> 4) * 8;
                int bcol = k0 + ((lane >> 3) & 1) * 8;
                uint32_t off = (uint32_t)(brow * STR + bcol) * 2;
                uint32_t bh[4], bl[4];
                ldm_x4(bh[0], bh[1], bh[2], bh[3], stage + 1 * MAT_H * 2 + off);
                ldm_x4(bl[0], bl[1], bl[2], bl[3], stage + 2 * MAT_H * 2 + off);
                #pragma unroll
                for (int nt2 = 0; nt2 < 2; nt2++) {
                    const int nt = ntp * 2 + nt2;
                    #pragma unroll
                    for (int mt = 0; mt < 2; mt++) {
                        mma_f16(C[mt][nt], ah[mt], &bh[nt2 * 2]);
                        mma_f16(C[mt][nt], ah[mt], &bl[nt2 * 2]);
                    }
                }
            }
        }
        __syncthreads();
    }

    // epilogue
    unsigned short* oh = (w == 0) ? g_Qh : (w == 1) ? g_Kh : g_Vh;
    unsigned short* ol = (w == 1) ? g_Kl : g_Vl;
    #pragma unroll
    for (int mt = 0; mt < 2; mt++) {
        #pragma unroll
        for (int nt = 0; nt < 8; nt++) {
            const float* d = C[mt][nt];
            int m = m0 + warp_m * 32 + mt * 16 + (lane >> 2);
            int n = n0 + warp_n * 64 + nt * 8 + (lane & 3) * 2;
            float b0 = bias[n], b1 = bias[n + 1];
            if (w < 3) {
                int h = n >> 6, dd = n & 63;
                #pragma unroll
                for (int rr = 0; rr < 2; rr++) {
                    int mm = m + rr * 8;
                    int bb = mm >> 10, ss = mm & 1023;
                    size_t o = ((size_t)(bb * NH_ + h) * S_ + ss) * HD_ + dd;
                    if (w == 0) {
                        *(uint32_t*)&oh[o] = pack2_f16(d[rr * 2 + 0] + b0, d[rr * 2 + 1] + b1);
                    } else {
                        uint32_t hi, lo;
                        pack_split_f16(d[rr * 2 + 0] + b0, d[rr * 2 + 1] + b1, hi, lo);
                        *(uint32_t*)&oh[o] = hi;
                        *(uint32_t*)&ol[o] = lo;
                    }
                }
            } else {
                #pragma unroll
                for (int rr = 0; rr < 2; rr++) {
                    int mm = m + rr * 8;
                    size_t idx = (size_t)mm * H_ + n;
                    float2 res = *(const float2*)&residual[idx];
                    float2 o = make_float2(d[rr * 2 + 0] + b0 + res.x,
                                           d[rr * 2 + 1] + b1 + res.y);
                    *(float2*)&g_x[idx] = o;
                }
            }
        }
    }
}

// ---------------------------------------------------------------------------
// Tensor-core flash attention, split-fp16 (2-pass), fp32 softmax.
// grid (S/128=8, B*NH=128), 256 thr (8 warps, 16 q-rows each).
// ---------------------------------------------------------------------------
#define ASTR 72   // smem row stride (u16)

__global__ __launch_bounds__(256) void attn_kernel(const float* __restrict__ mask)
{
    __shared__ unsigned short Kh[64 * ASTR], Kl[64 * ASTR];
    __shared__ unsigned short Vh[64 * ASTR], Vl[64 * ASTR];
    __shared__ float msk[S_];

    const int bh  = blockIdx.y;
    const int qt  = blockIdx.x;
    const int tid = threadIdx.x;
    const int wid = tid >> 5;
    const int lane = tid & 31;
    const int b   = bh >> 4;
    const int h   = bh & 15;
    const size_t base = (size_t)bh * S_ * HD_;

    const uint32_t sKh = smem_u32(Kh), sKl = smem_u32(Kl);
    const uint32_t sVh = smem_u32(Vh), sVl = smem_u32(Vl);

    // mask row -> smem (1024 floats, 256 threads)
    ((float4*)msk)[tid] = ((const float4*)(mask + (size_t)b * S_))[tid];

    // stage Q hi (128 rows): rows 0-63 -> Kh, 64-127 -> Vh
    #pragma unroll
    for (int t = 0; t < 4; t++) {
        int idx = tid + t * 256;            // 0..1023
        int row = idx >> 3, g = (idx & 7) * 8;
        size_t go = base + (size_t)(qt * 128 + row) * HD_ + g;
        unsigned short* dh = (row < 64) ? Kh : Vh;
        int r = row & 63;
        *(uint4*)&dh[r * ASTR + g] = *(const uint4*)&g_Qh[go];
    }
    __syncthreads();

    uint32_t qh[4][4];
    {
        const uint32_t bh_ = (wid < 4) ? sKh : sVh;
        int rbase = (wid & 3) * 16 + (lane & 15);
        #pragma unroll
        for (int ks = 0; ks < 4; ks++) {
            int col = ks * 16 + (lane >> 4) * 8;
            uint32_t off = (uint32_t)(rbase * ASTR + col) * 2;
            ldm_x4(qh[ks][0], qh[ks][1], qh[ks][2], qh[ks][3], bh_ + off);
        }
    }
    __syncthreads();

    float Co[8][4];
    #pragma unroll
    for (int i = 0; i < 8; i++)
        #pragma unroll
        for (int j = 0; j < 4; j++) Co[i][j] = 0.f;
    float m0 = -CUDART_INF_F, m1 = -CUDART_INF_F, l0 = 0.f, l1 = 0.f;

    for (int kt = 0; kt < S_ / 64; kt++) {
        // load K/V hi+lo tiles (64 rows each)
        #pragma unroll
        for (int t = 0; t < 2; t++) {
            int idx = tid + t * 256;        // 0..511
            int row = idx >> 3, g = (idx & 7) * 8;
            size_t go = base + (size_t)(kt * 64 + row) * HD_ + g;
            *(uint4*)&Kh[row * ASTR + g] = *(const uint4*)&g_Kh[go];
            *(uint4*)&Kl[row * ASTR + g] = *(const uint4*)&g_Kl[go];
            *(uint4*)&Vh[row * ASTR + g] = *(const uint4*)&g_Vh[go];
            *(uint4*)&Vl[row * ASTR + g] = *(const uint4*)&g_Vl[go];
        }
        __syncthreads();

        // S = Q K^T (2 passes: qh*kh + qh*kl)
        float Cs[8][4];
        #pragma unroll
        for (int i = 0; i < 8; i++)
            #pragma unroll
            for (int j = 0; j < 4; j++) Cs[i][j] = 0.f;

        #pragma unroll
        for (int ks = 0; ks < 4; ks++) {
            #pragma unroll
            for (int ntp = 0; ntp < 4; ntp++) {
                int brow = ntp * 16 + (lane & 7) + (lane >> 4) * 8;
                int bcol = ks * 16 + ((lane >> 3) & 1) * 8;
                uint32_t off = (uint32_t)(brow * ASTR + bcol) * 2;
                uint32_t kbh[4], kbl[4];
                ldm_x4(kbh[0], kbh[1], kbh[2], kbh[3], sKh + off);
                ldm_x4(kbl[0], kbl[1], kbl[2], kbl[3], sKl + off);
                #pragma unroll
                for (int nt2 = 0; nt2 < 2; nt2++) {
                    const int nt = ntp * 2 + nt2;
                    mma_f16(Cs[nt], qh[ks], &kbh[nt2 * 2]);
                    mma_f16(Cs[nt], qh[ks], &kbl[nt2 * 2]);
                }
            }
        }

        // scale + mask + online softmax
        float mn0 = m0, mn1 = m1;
        #pragma unroll
        for (int nt = 0; nt < 8; nt++) {
            int col = kt * 64 + nt * 8 + (lane & 3) * 2;
            float mka = msk[col], mkb = msk[col + 1];
            Cs[nt][0] = fmaf(Cs[nt][0], 0.125f, mka);
            Cs[nt][1] = fmaf(Cs[nt][1], 0.125f, mkb);
            Cs[nt][2] = fmaf(Cs[nt][2], 0.125f, mka);
            Cs[nt][3] = fmaf(Cs[nt][3], 0.125f, mkb);
            mn0 = fmaxf(mn0, fmaxf(Cs[nt][0], Cs[nt][1]));
            mn1 = fmaxf(mn1, fmaxf(Cs[nt][2], Cs[nt][3]));
        }
        mn0 = fmaxf(mn0, __shfl_xor_sync(0xffffffffu, mn0, 1));
        mn0 = fmaxf(mn0, __shfl_xor_sync(0xffffffffu, mn0, 2));
        mn1 = fmaxf(mn1, __shfl_xor_sync(0xffffffffu, mn1, 1));
        mn1 = fmaxf(mn1, __shfl_xor_sync(0xffffffffu, mn1, 2));

        float f0 = __expf(m0 - mn0), f1 = __expf(m1 - mn1);
        m0 = mn0; m1 = mn1;
        l0 *= f0; l1 *= f1;
        #pragma unroll
        for (int nt = 0; nt < 8; nt++) {
            Co[nt][0] *= f0; Co[nt][1] *= f0;
            Co[nt][2] *= f1; Co[nt][3] *= f1;
        }
        #pragma unroll
        for (int nt = 0; nt < 8; nt++) {
            Cs[nt][0] = __expf(Cs[nt][0] - m0);
            Cs[nt][1] = __expf(Cs[nt][1] - m0);
            Cs[nt][2] = __expf(Cs[nt][2] - m1);
            Cs[nt][3] = __expf(Cs[nt][3] - m1);
            l0 += Cs[nt][0] + Cs[nt][1];
            l1 += Cs[nt][2] + Cs[nt][3];
        }

        // O += P V (2 passes: ph*vh + ph*vl)
        #pragma unroll
        for (int kc = 0; kc < 4; kc++) {
            uint32_t phi[4];
            phi[0] = pack2_f16(Cs[2 * kc][0],     Cs[2 * kc][1]);
            phi[1] = pack2_f16(Cs[2 * kc][2],     Cs[2 * kc][3]);
            phi[2] = pack2_f16(Cs[2 * kc + 1][0], Cs[2 * kc + 1][1]);
            phi[3] = pack2_f16(Cs[2 * kc + 1][2], Cs[2 * kc + 1][3]);
            #pragma unroll
            for (int ntp = 0; ntp < 4; ntp++) {
                uint32_t off = (uint32_t)((kc * 16 + (lane & 15)) * ASTR +
                                          ntp * 16 + (lane >> 4) * 8) * 2;
                uint32_t vbh[4], vbl[4];
                ldm_x4_t(vbh[0], vbh[1], vbh[2], vbh[3], sVh + off);
                ldm_x4_t(vbl[0], vbl[1], vbl[2], vbl[3], sVl + off);
                #pragma unroll
                for (int nt2 = 0; nt2 < 2; nt2++) {
                    const int nt = ntp * 2 + nt2;
                    mma_f16(Co[nt], phi, &vbh[nt2 * 2]);
                    mma_f16(Co[nt], phi, &vbl[nt2 * 2]);
                }
            }
        }
        __syncthreads();
    }

    l0 += __shfl_xor_sync(0xffffffffu, l0, 1);
    l0 += __shfl_xor_sync(0xffffffffu, l0, 2);
    l1 += __shfl_xor_sync(0xffffffffu, l1, 1);
    l1 += __shfl_xor_sync(0xffffffffu, l1, 2);
    float inv0 = 1.f / l0, inv1 = 1.f / l1;

    const int s0 = qt * 128 + wid * 16 + (lane >> 2);
    #pragma unroll
    for (int nt = 0; nt < 8; nt++) {
        int col = h * HD_ + nt * 8 + (lane & 3) * 2;
        size_t o0 = (size_t)(b * S_ + s0) * H_ + col;
        size_t o1 = (size_t)(b * S_ + s0 + 8) * H_ + col;
        *(uint32_t*)&g_Chi[o0] = pack2_f16(Co[nt][0] * inv0, Co[nt][1] * inv0);
        *(uint32_t*)&g_Chi[o1] = pack2_f16(Co[nt][2] * inv1, Co[nt][3] * inv1);
    }
}

// ---------------------------------------------------------------------------
// LayerNorm
// ---------------------------------------------------------------------------
__global__ __launch_bounds__(256) void ln_kernel(
    const float* __restrict__ gamma, const float* __restrict__ beta,
    float* __restrict__ out)
{
    const int row = blockIdx.x;
    const int tid = threadIdx.x;
    const float* x = g_x + (size_t)row * H_;

    float4 v = *(const float4*)&x[tid * 4];
    float s  = v.x + v.y + v.z + v.w;
    float ss = v.x * v.x + v.y * v.y + v.z * v.z + v.w * v.w;

    #pragma unroll
    for (int o = 16; o > 0; o >>= 1) {
        s  += __shfl_xor_sync(0xffffffffu, s,  o);
        ss += __shfl_xor_sync(0xffffffffu, ss, o);
    }
    __shared__ float rs[8], rss[8];
    int wid = tid >> 5, lid = tid & 31;
    if (lid == 0) { rs[wid] = s; rss[wid] = ss; }
    __syncthreads();
    if (wid == 0) {
        float a = (lid < 8) ? rs[lid]  : 0.f;
        float c = (lid < 8) ? rss[lid] : 0.f;
        #pragma unroll
        for (int o = 4; o > 0; o >>= 1) {
            a += __shfl_xor_sync(0xffffffffu, a, o);
            c += __shfl_xor_sync(0xffffffffu, c, o);
        }
        if (lid == 0) { rs[0] = a; rss[0] = c; }
    }
    __syncthreads();

    float mean = rs[0] * (1.f / H_);
    float var  = rss[0] * (1.f / H_) - mean * mean;
    float rstd = rsqrtf(var + LN_EPS);

    float4 g = *(const float4*)&gamma[tid * 4];
    float4 bt = *(const float4*)&beta[tid * 4];
    float4 y;
    y.x = (v.x - mean) * rstd * g.x + bt.x;
    y.y = (v.y - mean) * rstd * g.y + bt.y;
    y.z = (v.z - mean) * rstd * g.z + bt.z;
    y.w = (v.w - mean) * rstd * g.w + bt.w;
    *(float4*)&out[(size_t)row * H_ + tid * 4] = y;
}

// ---------------------------------------------------------------------------
extern "C" void kernel_launch(void* const* d_in, const int* in_sizes, int n_in,
                              void* d_out, int out_size)
{
    const float* hidden = (const float*)d_in[0];
    const float* mask   = (const float*)d_in[1];
    const float* Wq     = (const float*)d_in[2];
    const float* bq     = (const float*)d_in[3];
    const float* Wk     = (const float*)d_in[4];
    const float* bk     = (const float*)d_in[5];
    const float* Wv     = (const float*)d_in[6];
    const float* bv     = (const float*)d_in[7];
    const float* Wo     = (const float*)d_in[8];
    const float* bo     = (const float*)d_in[9];
    const float* gamma  = (const float*)d_in[10];
    const float* beta   = (const float*)d_in[11];
    float* out          = (float*)d_out;

    static int attr_set = 0;
    if (!attr_set) {
        cudaFuncSetAttribute(gemm_kernel, cudaFuncAttributeMaxDynamicSharedMemorySize, GEMM_SMEM);
        attr_set = 1;
    }

    unsigned short *xhi, *whi, *wlo, *chi;
    cudaGetSymbolAddress((void**)&xhi, g_Xhi);
    cudaGetSymbolAddress((void**)&whi, g_Whi);
    cudaGetSymbolAddress((void**)&wlo, g_Wlo);
    cudaGetSymbolAddress((void**)&chi, g_Chi);

    const int NW = H_ * H_ / 4;
    split_hi_kernel<<<(M_ * H_ / 4 + 255) / 256, 256>>>(hidden, xhi, M_ * H_ / 4);
    split_hilo_kernel<<<(NW + 255) / 256, 256>>>(Wq, whi + 0 * H_ * H_, wlo + 0 * H_ * H_, NW);
    split_hilo_kernel<<<(NW + 255) / 256, 256>>>(Wk, whi + 1 * H_ * H_, wlo + 1 * H_ * H_, NW);
    split_hilo_kernel<<<(NW + 255) / 256, 256>>>(Wv, whi + 2 * H_ * H_, wlo + 2 * H_ * H_, NW);
    split_hilo_kernel<<<(NW + 255) / 256, 256>>>(Wo, whi + 3 * H_ * H_, wlo + 3 * H_ * H_, NW);

    dim3 qkv_grid(H_ / 128, M_ / 128, 3);
    gemm_kernel<<<qkv_grid, 256, GEMM_SMEM>>>(xhi, 0, bq, bk, bv, nullptr);

    dim3 attn_grid(S_ / 128, B_ * NH_);
    attn_kernel<<<attn_grid, 256>>>(mask);

    dim3 out_grid(H_ / 128, M_ / 128, 1);
    gemm_kernel<<<out_grid, 256, GEMM_SMEM>>>(chi, 3, bo, nullptr, nullptr, hidden);

    ln_kernel<<<M_, 256>>>(gamma, beta, out);
}

// round 11
// speedup vs baseline: 2.5826x; 1.6354x over previous
#include <cuda_runtime.h>
#include <cuda_fp16.h>
#include <math_constants.h>
#include <cstdint>

#define B_ 8
#define S_ 1024
#define H_ 1024
#define NH_ 16
#define HD_ 64
#define M_ (B_ * S_)        // 8192
#define LN_EPS 1e-12f

// fp32 scratch
__device__ float g_x[M_ * H_];    // residual-added pre-LN

// fp16 scratch (u16 bits)
__device__ unsigned short g_Xhi[M_ * H_];
__device__ unsigned short g_Whi[4 * H_ * H_];   // Wq,Wk,Wv,Wo
__device__ unsigned short g_Qh[M_ * H_];        // [B*NH][S][HD]
__device__ unsigned short g_Kh[M_ * H_];
__device__ unsigned short g_Vh[M_ * H_];
__device__ unsigned short g_Chi[M_ * H_];       // ctx fp16 [B,S,H]

// ---------------------------------------------------------------------------
// helpers (family-agnostic PTX: ldmatrix sm_75+, mma.sync f16 + cp.async sm_80+)
// ---------------------------------------------------------------------------
__device__ __forceinline__ uint32_t smem_u32(const void* p) {
    uint32_t a;
    asm("{ .reg .u64 t; cvta.to.shared.u64 t, %1; cvt.u32.u64 %0, t; }" : "=r"(a) : "l"(p));
    return a;
}
__device__ __forceinline__ void ldm_x4(uint32_t& r0, uint32_t& r1, uint32_t& r2, uint32_t& r3,
                                       uint32_t addr) {
    asm volatile("ldmatrix.sync.aligned.m8n8.x4.shared.b16 {%0,%1,%2,%3}, [%4];"
                 : "=r"(r0), "=r"(r1), "=r"(r2), "=r"(r3) : "r"(addr));
}
__device__ __forceinline__ void ldm_x4_t(uint32_t& r0, uint32_t& r1, uint32_t& r2, uint32_t& r3,
                                         uint32_t addr) {
    asm volatile("ldmatrix.sync.aligned.m8n8.x4.trans.shared.b16 {%0,%1,%2,%3}, [%4];"
                 : "=r"(r0), "=r"(r1), "=r"(r2), "=r"(r3) : "r"(addr));
}
__device__ __forceinline__ void mma_f16(float* d, const uint32_t* a, const uint32_t* b) {
    asm volatile(
        "mma.sync.aligned.m16n8k16.row.col.f32.f16.f16.f32 "
        "{%0,%1,%2,%3}, {%4,%5,%6,%7}, {%8,%9}, {%0,%1,%2,%3};"
        : "+f"(d[0]), "+f"(d[1]), "+f"(d[2]), "+f"(d[3])
        : "r"(a[0]), "r"(a[1]), "r"(a[2]), "r"(a[3]), "r"(b[0]), "r"(b[1]));
}
__device__ __forceinline__ void cp16(uint32_t dst, const void* src) {
    asm volatile("cp.async.cg.shared.global [%0], [%1], 16;" :: "r"(dst), "l"(src));
}
__device__ __forceinline__ void cp_commit() { asm volatile("cp.async.commit_group;"); }

__device__ __forceinline__ uint32_t pack2_f16(float a, float b) {
    __half ha = __float2half(a), hb = __float2half(b);
    return (uint32_t)__half_as_ushort(ha) | ((uint32_t)__half_as_ushort(hb) << 16);
}

// ---------------------------------------------------------------------------
// split fp32 -> fp16
// ---------------------------------------------------------------------------
__global__ __launch_bounds__(256) void split_hi_kernel(
    const float* __restrict__ src, unsigned short* __restrict__ hi, int n4)
{
    int i = blockIdx.x * 256 + threadIdx.x;
    if (i >= n4) return;
    float4 v = ((const float4*)src)[i];
    ushort4 hh;
    hh.x = __half_as_ushort(__float2half(v.x));
    hh.y = __half_as_ushort(__float2half(v.y));
    hh.z = __half_as_ushort(__float2half(v.z));
    hh.w = __half_as_ushort(__float2half(v.w));
    ((ushort4*)hi)[i] = hh;
}

// ---------------------------------------------------------------------------
// cp.async 2-stage fp16 GEMM: C[m][n] = sum_k A[m][k]*W[n][k]
// BM=128 BN=128 BK=64, 256 thr (8 warps 4x2), warp tile 32x64, single pass.
// Stage = 2 matrices (Ah,Bh) = 36 KB. Double buffer 72 KB -> 2 CTAs/SM.
// ---------------------------------------------------------------------------
#define BK 64
#define NCH (H_ / BK)        // 16
#define STR 72               // smem row stride (halves), 64 cols + 8 pad
#define MAT_H (128 * STR)    // 9216 halves
#define STG_H (2 * MAT_H)
#define GEMM_SMEM (2 * STG_H * 2)   // 73728 B

__global__ __launch_bounds__(256, 2) void gemm_kernel(
    const unsigned short* __restrict__ Ahi,
    int wbase,
    const float* __restrict__ bias0, const float* __restrict__ bias1,
    const float* __restrict__ bias2, const float* __restrict__ residual)
{
    extern __shared__ unsigned short sm[];
    const uint32_t sbase = smem_u32(sm);

    const int tid = threadIdx.x;
    const int wid = tid >> 5;
    const int lane = tid & 31;
    const int warp_m = wid & 3;
    const int warp_n = wid >> 2;
    const int w  = wbase + blockIdx.z;
    const int n0 = blockIdx.x * 128;
    const int m0 = blockIdx.y * 128;

    const unsigned short* Bhi = g_Whi + ((size_t)w << 20);
    const float* bias = (w == 1) ? bias1 : (w == 2) ? bias2 : bias0;

    const unsigned short* gsrc[2] = {Ahi, Bhi};
    const int gbase[2] = {m0, n0};

    auto issue_stage = [&](int c) {
        const int st = c & 1;
        const int kc = c * BK;
        #pragma unroll
        for (int t = 0; t < 8; t++) {
            int v = tid + t * 256;          // 0..2047
            int mat = v >> 10;
            int rem = v & 1023;
            int row = rem >> 3;
            int g = (rem & 7) * 8;
            const unsigned short* src = gsrc[mat] + (size_t)(gbase[mat] + row) * H_ + kc + g;
            uint32_t dst = sbase + (uint32_t)(st * STG_H + mat * MAT_H + row * STR + g) * 2;
            cp16(dst, src);
        }
        cp_commit();
    };

    float C[2][8][4];
    #pragma unroll
    for (int a = 0; a < 2; a++)
        #pragma unroll
        for (int b = 0; b < 8; b++)
            #pragma unroll
            for (int c = 0; c < 4; c++) C[a][b][c] = 0.f;

    issue_stage(0);

    for (int c = 0; c < NCH; c++) {
        if (c + 1 < NCH) {
            issue_stage(c + 1);
            asm volatile("cp.async.wait_group 1;" ::: "memory");
        } else {
            asm volatile("cp.async.wait_group 0;" ::: "memory");
        }
        __syncthreads();

        const uint32_t stage = sbase + (uint32_t)(c & 1) * (STG_H * 2);

        #pragma unroll
        for (int ks = 0; ks < 4; ks++) {
            const int k0 = ks * 16;
            uint32_t ah[2][4];
            #pragma unroll
            for (int mt = 0; mt < 2; mt++) {
                int row = warp_m * 32 + mt * 16 + (lane & 15);
                int col = k0 + (lane >> 4) * 8;
                uint32_t off = (uint32_t)(row * STR + col) * 2;
                ldm_x4(ah[mt][0], ah[mt][1], ah[mt][2], ah[mt][3], stage + off);
            }
            #pragma unroll
            for (int ntp = 0; ntp < 4; ntp++) {
                int brow = warp_n * 64 + ntp * 16 + (lane & 7) + (lane >> 4) * 8;
                int bcol = k0 + ((lane >> 3) & 1) * 8;
                uint32_t off = (uint32_t)(brow * STR + bcol) * 2;
                uint32_t bh[4];
                ldm_x4(bh[0], bh[1], bh[2], bh[3], stage + MAT_H * 2 + off);
                #pragma unroll
                for (int nt2 = 0; nt2 < 2; nt2++) {
                    const int nt = ntp * 2 + nt2;
                    #pragma unroll
                    for (int mt = 0; mt < 2; mt++) {
                        mma_f16(C[mt][nt], ah[mt], &bh[nt2 * 2]);
                    }
                }
            }
        }
        __syncthreads();
    }

    // epilogue
    unsigned short* oh = (w == 0) ? g_Qh : (w == 1) ? g_Kh : g_Vh;
    #pragma unroll
    for (int mt = 0; mt < 2; mt++) {
        #pragma unroll
        for (int nt = 0; nt < 8; nt++) {
            const float* d = C[mt][nt];
            int m = m0 + warp_m * 32 + mt * 16 + (lane >> 2);
            int n = n0 + warp_n * 64 + nt * 8 + (lane & 3) * 2;
            float b0 = bias[n], b1 = bias[n + 1];
            if (w < 3) {
                int h = n >> 6, dd = n & 63;
                #pragma unroll
                for (int rr = 0; rr < 2; rr++) {
                    int mm = m + rr * 8;
                    int bb = mm >> 10, ss = mm & 1023;
                    size_t o = ((size_t)(bb * NH_ + h) * S_ + ss) * HD_ + dd;
                    *(uint32_t*)&oh[o] = pack2_f16(d[rr * 2 + 0] + b0, d[rr * 2 + 1] + b1);
                }
            } else {
                #pragma unroll
                for (int rr = 0; rr < 2; rr++) {
                    int mm = m + rr * 8;
                    size_t idx = (size_t)mm * H_ + n;
                    float2 res = *(const float2*)&residual[idx];
                    float2 o = make_float2(d[rr * 2 + 0] + b0 + res.x,
                                           d[rr * 2 + 1] + b1 + res.y);
                    *(float2*)&g_x[idx] = o;
                }
            }
        }
    }
}

// ---------------------------------------------------------------------------
// Tensor-core flash attention, fp16 single pass, fp32 softmax.
// grid (S/128=8, B*NH=128), 256 thr (8 warps, 16 q-rows each).
// ---------------------------------------------------------------------------
#define ASTR 72   // smem row stride (u16)

__global__ __launch_bounds__(256) void attn_kernel(const float* __restrict__ mask)
{
    __shared__ unsigned short Kh[64 * ASTR];
    __shared__ unsigned short Vh[64 * ASTR];
    __shared__ float msk[S_];

    const int bh  = blockIdx.y;
    const int qt  = blockIdx.x;
    const int tid = threadIdx.x;
    const int wid = tid >> 5;
    const int lane = tid & 31;
    const int b   = bh >> 4;
    const int h   = bh & 15;
    const size_t base = (size_t)bh * S_ * HD_;

    const uint32_t sKh = smem_u32(Kh);
    const uint32_t sVh = smem_u32(Vh);

    // mask row -> smem (1024 floats, 256 threads)
    ((float4*)msk)[tid] = ((const float4*)(mask + (size_t)b * S_))[tid];

    // stage Q (128 rows): rows 0-63 -> Kh, 64-127 -> Vh
    #pragma unroll
    for (int t = 0; t < 4; t++) {
        int idx = tid + t * 256;            // 0..1023
        int row = idx >> 3, g = (idx & 7) * 8;
        size_t go = base + (size_t)(qt * 128 + row) * HD_ + g;
        unsigned short* dh = (row < 64) ? Kh : Vh;
        int r = row & 63;
        *(uint4*)&dh[r * ASTR + g] = *(const uint4*)&g_Qh[go];
    }
    __syncthreads();

    uint32_t qh[4][4];
    {
        const uint32_t bh_ = (wid < 4) ? sKh : sVh;
        int rbase = (wid & 3) * 16 + (lane & 15);
        #pragma unroll
        for (int ks = 0; ks < 4; ks++) {
            int col = ks * 16 + (lane >> 4) * 8;
            uint32_t off = (uint32_t)(rbase * ASTR + col) * 2;
            ldm_x4(qh[ks][0], qh[ks][1], qh[ks][2], qh[ks][3], bh_ + off);
        }
    }
    __syncthreads();

    float Co[8][4];
    #pragma unroll
    for (int i = 0; i < 8; i++)
        #pragma unroll
        for (int j = 0; j < 4; j++) Co[i][j] = 0.f;
    float m0 = -CUDART_INF_F, m1 = -CUDART_INF_F, l0 = 0.f, l1 = 0.f;

    for (int kt = 0; kt < S_ / 64; kt++) {
        // load K/V tiles (64 rows each)
        {
            int idx = tid;                  // 0..255 -> 2 uint4 per thread per matrix? 512 transfers needed
            #pragma unroll
            for (int t = 0; t < 2; t++) {
                int v = tid + t * 256;      // 0..511
                int row = v >> 3, g = (v & 7) * 8;
                size_t go = base + (size_t)(kt * 64 + row) * HD_ + g;
                *(uint4*)&Kh[row * ASTR + g] = *(const uint4*)&g_Kh[go];
                *(uint4*)&Vh[row * ASTR + g] = *(const uint4*)&g_Vh[go];
            }
            (void)idx;
        }
        __syncthreads();

        // S = Q K^T (single pass)
        float Cs[8][4];
        #pragma unroll
        for (int i = 0; i < 8; i++)
            #pragma unroll
            for (int j = 0; j < 4; j++) Cs[i][j] = 0.f;

        #pragma unroll
        for (int ks = 0; ks < 4; ks++) {
            #pragma unroll
            for (int ntp = 0; ntp < 4; ntp++) {
                int brow = ntp * 16 + (lane & 7) + (lane >> 4) * 8;
                int bcol = ks * 16 + ((lane >> 3) & 1) * 8;
                uint32_t off = (uint32_t)(brow * ASTR + bcol) * 2;
                uint32_t kbh[4];
                ldm_x4(kbh[0], kbh[1], kbh[2], kbh[3], sKh + off);
                #pragma unroll
                for (int nt2 = 0; nt2 < 2; nt2++) {
                    mma_f16(Cs[ntp * 2 + nt2], qh[ks], &kbh[nt2 * 2]);
                }
            }
        }

        // scale + mask + online softmax
        float mn0 = m0, mn1 = m1;
        #pragma unroll
        for (int nt = 0; nt < 8; nt++) {
            int col = kt * 64 + nt * 8 + (lane & 3) * 2;
            float mka = msk[col], mkb = msk[col + 1];
            Cs[nt][0] = fmaf(Cs[nt][0], 0.125f, mka);
            Cs[nt][1] = fmaf(Cs[nt][1], 0.125f, mkb);
            Cs[nt][2] = fmaf(Cs[nt][2], 0.125f, mka);
            Cs[nt][3] = fmaf(Cs[nt][3], 0.125f, mkb);
            mn0 = fmaxf(mn0, fmaxf(Cs[nt][0], Cs[nt][1]));
            mn1 = fmaxf(mn1, fmaxf(Cs[nt][2], Cs[nt][3]));
        }
        mn0 = fmaxf(mn0, __shfl_xor_sync(0xffffffffu, mn0, 1));
        mn0 = fmaxf(mn0, __shfl_xor_sync(0xffffffffu, mn0, 2));
        mn1 = fmaxf(mn1, __shfl_xor_sync(0xffffffffu, mn1, 1));
        mn1 = fmaxf(mn1, __shfl_xor_sync(0xffffffffu, mn1, 2));

        float f0 = __expf(m0 - mn0), f1 = __expf(m1 - mn1);
        m0 = mn0; m1 = mn1;
        l0 *= f0; l1 *= f1;
        #pragma unroll
        for (int nt = 0; nt < 8; nt++) {
            Co[nt][0] *= f0; Co[nt][1] *= f0;
            Co[nt][2] *= f1; Co[nt][3] *= f1;
        }
        #pragma unroll
        for (int nt = 0; nt < 8; nt++) {
            Cs[nt][0] = __expf(Cs[nt][0] - m0);
            Cs[nt][1] = __expf(Cs[nt][1] - m0);
            Cs[nt][2] = __expf(Cs[nt][2] - m1);
            Cs[nt][3] = __expf(Cs[nt][3] - m1);
            l0 += Cs[nt][0] + Cs[nt][1];
            l1 += Cs[nt][2] + Cs[nt][3];
        }

        // O += P V (single pass)
        #pragma unroll
        for (int kc = 0; kc < 4; kc++) {
            uint32_t phi[4];
            phi[0] = pack2_f16(Cs[2 * kc][0],     Cs[2 * kc][1]);
            phi[1] = pack2_f16(Cs[2 * kc][2],     Cs[2 * kc][3]);
            phi[2] = pack2_f16(Cs[2 * kc + 1][0], Cs[2 * kc + 1][1]);
            phi[3] = pack2_f16(Cs[2 * kc + 1][2], Cs[2 * kc + 1][3]);
            #pragma unroll
            for (int ntp = 0; ntp < 4; ntp++) {
                uint32_t off = (uint32_t)((kc * 16 + (lane & 15)) * ASTR +
                                          ntp * 16 + (lane >> 4) * 8) * 2;
                uint32_t vbh[4];
                ldm_x4_t(vbh[0], vbh[1], vbh[2], vbh[3], sVh + off);
                #pragma unroll
                for (int nt2 = 0; nt2 < 2; nt2++) {
                    mma_f16(Co[ntp * 2 + nt2], phi, &vbh[nt2 * 2]);
                }
            }
        }
        __syncthreads();
    }

    l0 += __shfl_xor_sync(0xffffffffu, l0, 1);
    l0 += __shfl_xor_sync(0xffffffffu, l0, 2);
    l1 += __shfl_xor_sync(0xffffffffu, l1, 1);
    l1 += __shfl_xor_sync(0xffffffffu, l1, 2);
    float inv0 = 1.f / l0, inv1 = 1.f / l1;

    const int s0 = qt * 128 + wid * 16 + (lane >> 2);
    #pragma unroll
    for (int nt = 0; nt < 8; nt++) {
        int col = h * HD_ + nt * 8 + (lane & 3) * 2;
        size_t o0 = (size_t)(b * S_ + s0) * H_ + col;
        size_t o1 = (size_t)(b * S_ + s0 + 8) * H_ + col;
        *(uint32_t*)&g_Chi[o0] = pack2_f16(Co[nt][0] * inv0, Co[nt][1] * inv0);
        *(uint32_t*)&g_Chi[o1] = pack2_f16(Co[nt][2] * inv1, Co[nt][3] * inv1);
    }
}

// ---------------------------------------------------------------------------
// LayerNorm
// ---------------------------------------------------------------------------
__global__ __launch_bounds__(256) void ln_kernel(
    const float* __restrict__ gamma, const float* __restrict__ beta,
    float* __restrict__ out)
{
    const int row = blockIdx.x;
    const int tid = threadIdx.x;
    const float* x = g_x + (size_t)row * H_;

    float4 v = *(const float4*)&x[tid * 4];
    float s  = v.x + v.y + v.z + v.w;
    float ss = v.x * v.x + v.y * v.y + v.z * v.z + v.w * v.w;

    #pragma unroll
    for (int o = 16; o > 0; o >>= 1) {
        s  += __shfl_xor_sync(0xffffffffu, s,  o);
        ss += __shfl_xor_sync(0xffffffffu, ss, o);
    }
    __shared__ float rs[8], rss[8];
    int wid = tid >> 5, lid = tid & 31;
    if (lid == 0) { rs[wid] = s; rss[wid] = ss; }
    __syncthreads();
    if (wid == 0) {
        float a = (lid < 8) ? rs[lid]  : 0.f;
        float c = (lid < 8) ? rss[lid] : 0.f;
        #pragma unroll
        for (int o = 4; o > 0; o >>= 1) {
            a += __shfl_xor_sync(0xffffffffu, a, o);
            c += __shfl_xor_sync(0xffffffffu, c, o);
        }
        if (lid == 0) { rs[0] = a; rss[0] = c; }
    }
    __syncthreads();

    float mean = rs[0] * (1.f / H_);
    float var  = rss[0] * (1.f / H_) - mean * mean;
    float rstd = rsqrtf(var + LN_EPS);

    float4 g = *(const float4*)&gamma[tid * 4];
    float4 bt = *(const float4*)&beta[tid * 4];
    float4 y;
    y.x = (v.x - mean) * rstd * g.x + bt.x;
    y.y = (v.y - mean) * rstd * g.y + bt.y;
    y.z = (v.z - mean) * rstd * g.z + bt.z;
    y.w = (v.w - mean) * rstd * g.w + bt.w;
    *(float4*)&out[(size_t)row * H_ + tid * 4] = y;
}

// ---------------------------------------------------------------------------
extern "C" void kernel_launch(void* const* d_in, const int* in_sizes, int n_in,
                              void* d_out, int out_size)
{
    const float* hidden = (const float*)d_in[0];
    const float* mask   = (const float*)d_in[1];
    const float* Wq     = (const float*)d_in[2];
    const float* bq     = (const float*)d_in[3];
    const float* Wk     = (const float*)d_in[4];
    const float* bk     = (const float*)d_in[5];
    const float* Wv     = (const float*)d_in[6];
    const float* bv     = (const float*)d_in[7];
    const float* Wo     = (const float*)d_in[8];
    const float* bo     = (const float*)d_in[9];
    const float* gamma  = (const float*)d_in[10];
    const float* beta   = (const float*)d_in[11];
    float* out          = (float*)d_out;

    static int attr_set = 0;
    if (!attr_set) {
        cudaFuncSetAttribute(gemm_kernel, cudaFuncAttributeMaxDynamicSharedMemorySize, GEMM_SMEM);
        attr_set = 1;
    }

    unsigned short *xhi, *whi, *chi;
    cudaGetSymbolAddress((void**)&xhi, g_Xhi);
    cudaGetSymbolAddress((void**)&whi, g_Whi);
    cudaGetSymbolAddress((void**)&chi, g_Chi);

    const int NW = H_ * H_ / 4;
    split_hi_kernel<<<(M_ * H_ / 4 + 255) / 256, 256>>>(hidden, xhi, M_ * H_ / 4);
    split_hi_kernel<<<(NW + 255) / 256, 256>>>(Wq, whi + 0 * H_ * H_, NW);
    split_hi_kernel<<<(NW + 255) / 256, 256>>>(Wk, whi + 1 * H_ * H_, NW);
    split_hi_kernel<<<(NW + 255) / 256, 256>>>(Wv, whi + 2 * H_ * H_, NW);
    split_hi_kernel<<<(NW + 255) / 256, 256>>>(Wo, whi + 3 * H_ * H_, NW);

    dim3 qkv_grid(H_ / 128, M_ / 128, 3);
    gemm_kernel<<<qkv_grid, 256, GEMM_SMEM>>>(xhi, 0, bq, bk, bv, nullptr);

    dim3 attn_grid(S_ / 128, B_ * NH_);
    attn_kernel<<<attn_grid, 256>>>(mask);

    dim3 out_grid(H_ / 128, M_ / 128, 1);
    gemm_kernel<<<out_grid, 256, GEMM_SMEM>>>(chi, 3, bo, nullptr, nullptr, hidden);

    ln_kernel<<<M_, 256>>>(gamma, beta, out);
}